// round 4
// baseline (speedup 1.0000x reference)
#include <cuda_runtime.h>
#include <math.h>

#define NB 16
#define NT 64
#define NV 32000
#define NE 256
#define NH 1024
#define NG 4096   // 4*H

// ---------------- device scratch (no allocs allowed) ----------------
__device__ float g_zx_enc[NB*NT*NG];     // precomputed x@W + bias (encoder)
__device__ float g_zx_dec[NB*NT*NG];     // precomputed x@W + bias (decoder)
__device__ float g_memory[NB*NT*NH];
__device__ float g_keys[NB*NT*NH];
__device__ float g_dec_out[NB*NT*NH];
__device__ float g_zpart[16*NB*NG];      // z-gemm K-split partials (4H wide)
__device__ float g_qpart[32*NB*NH];
__device__ float g_apart[32*NB*NH];
__device__ float g_h[NB*NH];
__device__ float g_c[NB*NH];
__device__ float g_attn_h[NB*2*NH];      // [attn(1024) | h(1024)] per batch (decoder input)
__device__ float g_h_ctx[NB*2*NH];       // [h2(1024) | context(1024)] per batch

__device__ __forceinline__ float sigm(float x){ return 1.f/(1.f + __expf(-x)); }
__device__ __forceinline__ float ftanh(float x){
  float a = fabsf(x);
  float e = __expf(-2.f * a);
  float t = (1.f - e) / (1.f + e);
  return copysignf(t, x);
}

__device__ __forceinline__ void fma2(unsigned long long &d,
                                     unsigned long long a, unsigned long long b){
  asm("fma.rn.f32x2 %0, %1, %2, %0;" : "+l"(d) : "l"(a), "l"(b));
}
__device__ __forceinline__ float2 u2f(unsigned long long u){
  float2 f; asm("mov.b64 {%0,%1}, %2;" : "=f"(f.x), "=f"(f.y) : "l"(u)); return f;
}

// =====================================================================
// f32x2 tiled SGEMM: C[M,N] = gatherA[M,K] @ W[K,N] (+bias).
// 128x128 tile, 256 threads, 8 rows x 4 f32x2-pairs per thread, BK=8.
// A stored duplicated in smem so the b64 A-operand needs no repack.
// Register double-buffered gmem loads. M,N,K multiples of tile dims.
// =====================================================================
__global__ __launch_bounds__(256, 2) void sgemm2(
    int M, int N, int K,
    const float* __restrict__ A, const float* __restrict__ W,
    const float* __restrict__ bias, float* __restrict__ C,
    const int* __restrict__ gather)
{
  __shared__ __align__(16) float2 As2[8][128];  // As2[k][m] = (a, a)
  __shared__ __align__(16) float  Bs[8][128];
  const int tid = threadIdx.x;
  const int tx = tid & 15;
  const int ty = tid >> 4;
  const int mbase = blockIdx.y * 128;
  const int nbase = blockIdx.x * 128;
  const int arow = tid >> 1;
  const int acol = (tid & 1) << 2;
  const int brow = tid >> 5;
  const int bcol = (tid & 31) << 2;
  const int arI = mbase + arow;
  const float* Ap = A + (size_t)(gather ? gather[arI] : arI) * K + acol;
  const float* Wp = W + (size_t)brow * N + nbase + bcol;

  unsigned long long acc[8][4];
#pragma unroll
  for (int i = 0; i < 8; i++)
#pragma unroll
    for (int j = 0; j < 4; j++) acc[i][j] = 0ull;

  float4 av = *(const float4*)(Ap);
  float4 bv = *(const float4*)(Wp);

  for (int k0 = 0; k0 < K; k0 += 8) {
    As2[acol+0][arow] = make_float2(av.x, av.x);
    As2[acol+1][arow] = make_float2(av.y, av.y);
    As2[acol+2][arow] = make_float2(av.z, av.z);
    As2[acol+3][arow] = make_float2(av.w, av.w);
    *(float4*)&Bs[brow][bcol] = bv;
    __syncthreads();
    if (k0 + 8 < K) {
      av = *(const float4*)(Ap + k0 + 8);
      bv = *(const float4*)(Wp + (size_t)(k0 + 8) * N);
    }
#pragma unroll
    for (int kk = 0; kk < 8; kk++) {
      ulonglong2 a0 = *(const ulonglong2*)(&As2[kk][ty*8 + 0]);
      ulonglong2 a1 = *(const ulonglong2*)(&As2[kk][ty*8 + 2]);
      ulonglong2 a2 = *(const ulonglong2*)(&As2[kk][ty*8 + 4]);
      ulonglong2 a3 = *(const ulonglong2*)(&As2[kk][ty*8 + 6]);
      ulonglong2 b0 = *(const ulonglong2*)(&Bs[kk][tx*8 + 0]);
      ulonglong2 b1 = *(const ulonglong2*)(&Bs[kk][tx*8 + 4]);
      unsigned long long ad[8] = {a0.x, a0.y, a1.x, a1.y, a2.x, a2.y, a3.x, a3.y};
      unsigned long long bd[4] = {b0.x, b0.y, b1.x, b1.y};
#pragma unroll
      for (int i = 0; i < 8; i++)
#pragma unroll
        for (int j = 0; j < 4; j++) fma2(acc[i][j], ad[i], bd[j]);
    }
    __syncthreads();
  }

  float bvals[8];
#pragma unroll
  for (int j = 0; j < 8; j++) bvals[j] = bias ? bias[nbase + tx*8 + j] : 0.f;
#pragma unroll
  for (int i = 0; i < 8; i++) {
    float* crow = C + (size_t)(mbase + ty*8 + i) * N + nbase + tx*8;
    float2 v0 = u2f(acc[i][0]);
    float2 v1 = u2f(acc[i][1]);
    float2 v2 = u2f(acc[i][2]);
    float2 v3 = u2f(acc[i][3]);
    float4 o0 = make_float4(v0.x + bvals[0], v0.y + bvals[1],
                            v1.x + bvals[2], v1.y + bvals[3]);
    float4 o1 = make_float4(v2.x + bvals[4], v2.y + bvals[5],
                            v3.x + bvals[6], v3.y + bvals[7]);
    *(float4*)(crow)     = o0;
    *(float4*)(crow + 4) = o1;
  }
}

// =====================================================================
// Skinny GEMM for M=16 recurrent matmuls, K-split, deterministic partials.
// Prefetches 4 W rows per iteration to raise loads-in-flight (MLP 1 -> 4).
// grid = (N/128, KSPLIT); block = 256. Kblk = K/gridDim.y, Kblk/8 % 4 == 0
// except the smallest case (kchunk==4 handled by the k+=4 loop trivially).
// =====================================================================
__global__ __launch_bounds__(256, 2) void skinny_gemm(
    const float* __restrict__ y, int ystride,
    const float* __restrict__ W, int ldw,
    float* __restrict__ part, int N, int K)
{
  __shared__ __align__(16) float smem[8192];
  const int tid  = threadIdx.x;
  const int wid  = tid >> 5;
  const int lane = tid & 31;
  const int Kblk  = K / gridDim.y;
  const int kbase = blockIdx.y * Kblk;
  const int c0    = blockIdx.x * 128 + lane * 4;

  // load y slab transposed into smem: ys[kl*16 + b]
  for (int idx = tid; idx < Kblk * 16; idx += 256) {
    int b = idx / Kblk;
    int kl = idx - b * Kblk;
    smem[kl*16 + b] = y[b * ystride + kbase + kl];
  }
  __syncthreads();

  const int kchunk = Kblk >> 3;
  const int ks0 = wid * kchunk;
  float4 acc[16];
#pragma unroll
  for (int b = 0; b < 16; b++) acc[b] = make_float4(0.f, 0.f, 0.f, 0.f);

  const float* Wp = W + (size_t)(kbase + ks0) * ldw + c0;
  const float4* yr = (const float4*)(smem + ks0 * 16);
  for (int k = 0; k < kchunk; k += 4) {
    float4 w[4];
#pragma unroll
    for (int u = 0; u < 4; u++) w[u] = *(const float4*)(Wp + (size_t)u * ldw);
    Wp += (size_t)4 * ldw;
#pragma unroll
    for (int u = 0; u < 4; u++) {
#pragma unroll
      for (int bq = 0; bq < 4; bq++) {
        float4 yv = yr[u*4 + bq];
        float ys4[4] = {yv.x, yv.y, yv.z, yv.w};
#pragma unroll
        for (int q = 0; q < 4; q++) {
          acc[4*bq+q].x += ys4[q] * w[u].x;
          acc[4*bq+q].y += ys4[q] * w[u].y;
          acc[4*bq+q].z += ys4[q] * w[u].z;
          acc[4*bq+q].w += ys4[q] * w[u].w;
        }
      }
    }
    yr += 16;
  }

  // cross-warp tree reduction in smem
  float4* red = (float4*)smem;   // [16][128] float4
#pragma unroll
  for (int s = 4; s > 0; s >>= 1) {
    __syncthreads();
    if (wid >= s && wid < 2*s) {
      int slot = (wid - s) * 32 + lane;
#pragma unroll
      for (int b = 0; b < 16; b++) red[b*128 + slot] = acc[b];
    }
    __syncthreads();
    if (wid < s) {
      int slot = wid * 32 + lane;
#pragma unroll
      for (int b = 0; b < 16; b++) {
        float4 r = red[b*128 + slot];
        acc[b].x += r.x; acc[b].y += r.y; acc[b].z += r.z; acc[b].w += r.w;
      }
    }
  }

  if (wid == 0) {
#pragma unroll
    for (int b = 0; b < 16; b++)
      *(float4*)(part + (size_t)(blockIdx.y*16 + b) * N + c0) = acc[b];
  }
}

// =====================================================================
// Elementwise / small kernels
// =====================================================================
__global__ void zero_state()
{
  int idx = blockIdx.x * 256 + threadIdx.x;   // 16384
  g_h[idx] = 0.f;
  g_c[idx] = 0.f;
}

__global__ void enc_step_gates(int t, int nsplit, const int* __restrict__ enc_len)
{
  int idx = blockIdx.x * 256 + threadIdx.x;   // 16384
  int b = idx >> 10, j = idx & 1023;
  size_t zo = (size_t)(b*NT + t) * NG + j;
  float zi = g_zx_enc[zo], zj = g_zx_enc[zo+1024];
  float zf = g_zx_enc[zo+2048], zoo = g_zx_enc[zo+3072];
  for (int s = 0; s < nsplit; s++) {
    size_t po = (size_t)(s*16 + b) * NG + j;
    zi += g_zpart[po]; zj += g_zpart[po+1024];
    zf += g_zpart[po+2048]; zoo += g_zpart[po+3072];
  }
  float cn = g_c[idx] * sigm(zf + 1.f) + sigm(zi) * ftanh(zj);
  float hn = ftanh(cn) * sigm(zoo);
  bool valid = t < enc_len[b];
  if (valid) { g_h[idx] = hn; g_c[idx] = cn; }
  g_memory[(size_t)(b*NT + t) * NH + j] = valid ? hn : 0.f;
}

__global__ void dec_init()
{
  int idx = blockIdx.x * 256 + threadIdx.x;   // 32768
  int b = idx >> 11, j = idx & 2047;
  g_attn_h[idx] = (j < 1024) ? 0.f : g_h[b*NH + (j - 1024)];
}

__global__ void dec_step_gates(int t, int nsplit)
{
  int idx = blockIdx.x * 256 + threadIdx.x;   // 16384
  int b = idx >> 10, j = idx & 1023;
  size_t zo = (size_t)(b*NT + t) * NG + j;
  float zi = g_zx_dec[zo], zj = g_zx_dec[zo+1024];
  float zf = g_zx_dec[zo+2048], zoo = g_zx_dec[zo+3072];
  for (int s = 0; s < nsplit; s++) {
    size_t po = (size_t)(s*16 + b) * NG + j;
    zi += g_zpart[po]; zj += g_zpart[po+1024];
    zf += g_zpart[po+2048]; zoo += g_zpart[po+3072];
  }
  float cn = g_c[idx] * sigm(zf + 1.f) + sigm(zi) * ftanh(zj);
  float hn = ftanh(cn) * sigm(zoo);
  g_c[idx] = cn;
  g_attn_h[b*2*NH + NH + j] = hn;   // h slot for next step's recurrent input
  g_h_ctx[b*2*NH + j] = hn;         // h2 slot for query/attn gemms
}

// Fused: q-partial reduce + scores (tanh dot) + mask + softmax + context.
// One block per batch (16 blocks, 256 threads).
__global__ __launch_bounds__(256) void fused_attn(
    int nsplit, const int* __restrict__ enc_len, const float* __restrict__ v_att)
{
  __shared__ float sq[NH];
  __shared__ float sal[NT];
  int b = blockIdx.x;
  int tid = threadIdx.x, wid = tid >> 5, lane = tid & 31;

  for (int h = tid; h < NH; h += 256) {
    float q = 0.f;
    for (int s = 0; s < nsplit; s++) q += g_qpart[(size_t)(s*16 + b) * NH + h];
    sq[h] = q;
  }
  __syncthreads();

  int L = enc_len[b];
  for (int tt = wid; tt < NT; tt += 8) {
    const float* krow = g_keys + (size_t)(b*NT + tt) * NH;
    float acc = 0.f;
    for (int h0 = lane; h0 < NH; h0 += 32)
      acc += ftanh(krow[h0] + sq[h0]) * v_att[h0];
#pragma unroll
    for (int o = 16; o; o >>= 1) acc += __shfl_xor_sync(0xffffffffu, acc, o);
    if (lane == 0) sal[tt] = (tt < L) ? acc : -1e9f;
  }
  __syncthreads();

  float mx = -3e38f;
#pragma unroll
  for (int t2 = 0; t2 < NT; t2++) mx = fmaxf(mx, sal[t2]);
  __syncthreads();
  if (tid < NT) sal[tid] = expf(sal[tid] - mx);
  __syncthreads();
  float sum = 0.f;
#pragma unroll
  for (int t2 = 0; t2 < NT; t2++) sum += sal[t2];
  float inv = 1.f / sum;

  for (int h = tid; h < NH; h += 256) {
    const float* mb = g_memory + (size_t)b * NT * NH + h;
    float ctx = 0.f;
#pragma unroll 8
    for (int t2 = 0; t2 < NT; t2++) ctx += sal[t2] * mb[(size_t)t2 * NH];
    g_h_ctx[b*2*NH + NH + h] = ctx * inv;
  }
}

__global__ void attn_out(int t, int nsplit, const int* __restrict__ dec_len)
{
  int idx = blockIdx.x * 256 + threadIdx.x;   // 16384
  int b = idx >> 10, j = idx & 1023;
  float a = 0.f;
  for (int s = 0; s < nsplit; s++) a += g_apart[(size_t)(s*16 + b) * NH + j];
  g_attn_h[b*2*NH + j] = a;   // attn carry (unmasked)
  g_dec_out[(size_t)(b*NT + t) * NH + j] = (t >= dec_len[b]) ? 0.f : a;
}

// =====================================================================
// Host launch
// =====================================================================
extern "C" void kernel_launch(void* const* d_in, const int* in_sizes, int n_in,
                              void* d_out, int out_size)
{
  const int*   enc_in      = (const int*)d_in[0];
  const int*   dec_in      = (const int*)d_in[1];
  const int*   enc_len     = (const int*)d_in[2];
  const int*   dec_len     = (const int*)d_in[3];
  const float* embedding   = (const float*)d_in[4];
  const float* enc_kernel  = (const float*)d_in[5];
  const float* enc_bias    = (const float*)d_in[6];
  const float* dec_kernel  = (const float*)d_in[7];
  const float* dec_bias    = (const float*)d_in[8];
  const float* Wm          = (const float*)d_in[9];
  const float* Wq          = (const float*)d_in[10];
  const float* v_att       = (const float*)d_in[11];
  const float* attn_kernel = (const float*)d_in[12];
  const float* out_kernel  = (const float*)d_in[13];
  float* out = (float*)d_out;
  (void)in_sizes; (void)n_in; (void)out_size;

  float *zx_enc, *zx_dec, *mem, *keys, *dec_o, *zpart, *qpart, *apart, *hbuf, *attn_h, *h_ctx;
  cudaGetSymbolAddress((void**)&zx_enc, g_zx_enc);
  cudaGetSymbolAddress((void**)&zx_dec, g_zx_dec);
  cudaGetSymbolAddress((void**)&mem,    g_memory);
  cudaGetSymbolAddress((void**)&keys,   g_keys);
  cudaGetSymbolAddress((void**)&dec_o,  g_dec_out);
  cudaGetSymbolAddress((void**)&zpart,  g_zpart);
  cudaGetSymbolAddress((void**)&qpart,  g_qpart);
  cudaGetSymbolAddress((void**)&apart,  g_apart);
  cudaGetSymbolAddress((void**)&hbuf,   g_h);
  cudaGetSymbolAddress((void**)&attn_h, g_attn_h);
  cudaGetSymbolAddress((void**)&h_ctx,  g_h_ctx);

  const float* enc_Wrec = enc_kernel + (size_t)NE * NG;  // rows E..E+H-1
  const float* dec_Wrec = dec_kernel + (size_t)NE * NG;  // rows E..E+2H-1

  // init state
  zero_state<<<64, 256>>>();

  // Zx precompute: emb-gather GEMMs [1024 x 4096 x 256] with bias
  sgemm2<<<dim3(32, 8), 256>>>(NB*NT, NG, NE, embedding, enc_kernel, enc_bias, zx_enc, enc_in);
  sgemm2<<<dim3(32, 8), 256>>>(NB*NT, NG, NE, embedding, dec_kernel, dec_bias, zx_dec, dec_in);

  // ---- encoder ----
  for (int t = 0; t < NT; t++) {
    skinny_gemm<<<dim3(32, 8), 256>>>(hbuf, NH, enc_Wrec, NG, zpart, NG, NH);
    enc_step_gates<<<64, 256>>>(t, 8, enc_len);
  }

  // keys = memory @ Wm  [1024 x 1024 x 1024]
  sgemm2<<<dim3(8, 8), 256>>>(NB*NT, NH, NH, mem, Wm, nullptr, keys, nullptr);

  // ---- decoder ----
  dec_init<<<128, 256>>>();
  for (int t = 0; t < NT; t++) {
    // z = zx + [attn|h] @ dec_kernel[E:,:]   (K = 2048, 16-way K split)
    skinny_gemm<<<dim3(32, 16), 256>>>(attn_h, 2*NH, dec_Wrec, NG, zpart, NG, 2*NH);
    dec_step_gates<<<64, 256>>>(t, 16);
    // query = h2 @ Wq   (K = 1024, 32-way K split)
    skinny_gemm<<<dim3(8, 32), 256>>>(h_ctx, 2*NH, Wq, NH, qpart, NH, NH);
    fused_attn<<<16, 256>>>(32, enc_len, v_att);
    // attn2 = [h2|context] @ attn_kernel   (K = 2048, 32-way K split)
    skinny_gemm<<<dim3(8, 32), 256>>>(h_ctx, 2*NH, attn_kernel, NH, apart, NH, 2*NH);
    attn_out<<<64, 256>>>(t, 32, dec_len);
  }

  // logits = dec_out @ out_kernel  [1024 x 32000 x 1024]
  sgemm2<<<dim3(250, 8), 256>>>(NB*NT, NV, NH, dec_o, out_kernel, nullptr, out, nullptr);
}

// round 5
// speedup vs baseline: 1.3998x; 1.3998x over previous
#include <cuda_runtime.h>
#include <math.h>

#define NB 16
#define NT 64
#define NV 32000
#define NE 256
#define NH 1024
#define NG 4096   // 4*H

// ---------------- device scratch (no allocs allowed) ----------------
__device__ float g_zx_enc[NB*NT*NG];     // precomputed x@W + bias (encoder)
__device__ float g_zx_dec[NB*NT*NG];     // precomputed x@W + bias (decoder)
__device__ float g_memory[NB*NT*NH];
__device__ float g_keys[NB*NT*NH];
__device__ float g_dec_out[NB*NT*NH];
__device__ float g_zpart[32*NB*NG];      // z-gemm K-split partials (4H wide)
__device__ float g_qpart[32*NB*NH];
__device__ float g_apart[32*NB*NH];
__device__ float g_h[NB*NH];
__device__ float g_c[NB*NH];
__device__ float g_attn_h[NB*2*NH];      // [attn(1024) | h(1024)] per batch (decoder input)
__device__ float g_h_ctx[NB*2*NH];       // [h2(1024) | context(1024)] per batch

__device__ __forceinline__ float sigm(float x){ return 1.f/(1.f + __expf(-x)); }
__device__ __forceinline__ float ftanh(float x){
  float a = fabsf(x);
  float e = __expf(-2.f * a);
  float t = (1.f - e) / (1.f + e);
  return copysignf(t, x);
}

// =====================================================================
// Big tiled SGEMM (R3-proven): C[M,N] = gatherA[M,K] @ W[K,N] (+bias).
// 128x128 tile, 256 threads, 8x8 per thread, BK=8.
// =====================================================================
__global__ __launch_bounds__(256) void sgemm_nn(
    int M, int N, int K,
    const float* __restrict__ A, const float* __restrict__ W,
    const float* __restrict__ bias, float* __restrict__ C,
    const int* __restrict__ gather)
{
  __shared__ float As[8][128];
  __shared__ float Bs[8][128];
  const int tid = threadIdx.x;
  const int tx = tid & 15;
  const int ty = tid >> 4;
  const int mbase = blockIdx.y * 128;
  const int nbase = blockIdx.x * 128;
  const int arow = tid >> 1;
  const int acol = (tid & 1) << 2;
  const int brow = tid >> 5;
  const int bcol = (tid & 31) << 2;
  const int arI = mbase + arow;
  const float* Ap = A + (size_t)(gather ? gather[arI] : arI) * K + acol;
  const float* Wp = W + (size_t)brow * N + nbase + bcol;

  float acc[8][8];
#pragma unroll
  for (int i = 0; i < 8; i++)
#pragma unroll
    for (int j = 0; j < 8; j++) acc[i][j] = 0.f;

  for (int k0 = 0; k0 < K; k0 += 8) {
    float4 av = *(const float4*)(Ap + k0);
    As[acol+0][arow] = av.x; As[acol+1][arow] = av.y;
    As[acol+2][arow] = av.z; As[acol+3][arow] = av.w;
    float4 bv = *(const float4*)(Wp + (size_t)k0 * N);
    *(float4*)&Bs[brow][bcol] = bv;
    __syncthreads();
#pragma unroll
    for (int kk = 0; kk < 8; kk++) {
      float ar[8], br[8];
#pragma unroll
      for (int i = 0; i < 8; i++) ar[i] = As[kk][ty*8 + i];
#pragma unroll
      for (int j = 0; j < 8; j++) br[j] = Bs[kk][tx*8 + j];
#pragma unroll
      for (int i = 0; i < 8; i++)
#pragma unroll
        for (int j = 0; j < 8; j++) acc[i][j] += ar[i] * br[j];
    }
    __syncthreads();
  }

  float bvals[8];
#pragma unroll
  for (int j = 0; j < 8; j++) bvals[j] = bias ? bias[nbase + tx*8 + j] : 0.f;
#pragma unroll
  for (int i = 0; i < 8; i++) {
    size_t ro = (size_t)(mbase + ty*8 + i) * N + nbase + tx*8;
#pragma unroll
    for (int j = 0; j < 8; j += 4) {
      float4 v;
      v.x = acc[i][j+0] + bvals[j+0];
      v.y = acc[i][j+1] + bvals[j+1];
      v.z = acc[i][j+2] + bvals[j+2];
      v.w = acc[i][j+3] + bvals[j+3];
      *(float4*)(C + ro + j) = v;
    }
  }
}

// =====================================================================
// Skinny GEMM for M=16 recurrent matmuls, K-split, deterministic partials.
// Prefetches 4 W rows per iteration (MLP=4). High K-split for latency hiding.
// grid = (N/128, KSPLIT); block = 256. Kblk = K/gridDim.y; kchunk = Kblk/8
// must be a multiple of 4 (or exactly 4).
// =====================================================================
__global__ __launch_bounds__(256, 2) void skinny_gemm(
    const float* __restrict__ y, int ystride,
    const float* __restrict__ W, int ldw,
    float* __restrict__ part, int N, int K)
{
  __shared__ __align__(16) float smem[8192];
  const int tid  = threadIdx.x;
  const int wid  = tid >> 5;
  const int lane = tid & 31;
  const int Kblk  = K / gridDim.y;
  const int kbase = blockIdx.y * Kblk;
  const int c0    = blockIdx.x * 128 + lane * 4;

  // load y slab transposed into smem: ys[kl*16 + b]
  for (int idx = tid; idx < Kblk * 16; idx += 256) {
    int b = idx / Kblk;
    int kl = idx - b * Kblk;
    smem[kl*16 + b] = y[b * ystride + kbase + kl];
  }
  __syncthreads();

  const int kchunk = Kblk >> 3;
  const int ks0 = wid * kchunk;
  float4 acc[16];
#pragma unroll
  for (int b = 0; b < 16; b++) acc[b] = make_float4(0.f, 0.f, 0.f, 0.f);

  const float* Wp = W + (size_t)(kbase + ks0) * ldw + c0;
  const float4* yr = (const float4*)(smem + ks0 * 16);
  for (int k = 0; k < kchunk; k += 4) {
    float4 w[4];
#pragma unroll
    for (int u = 0; u < 4; u++) w[u] = *(const float4*)(Wp + (size_t)u * ldw);
    Wp += (size_t)4 * ldw;
#pragma unroll
    for (int u = 0; u < 4; u++) {
#pragma unroll
      for (int bq = 0; bq < 4; bq++) {
        float4 yv = yr[u*4 + bq];
        float ys4[4] = {yv.x, yv.y, yv.z, yv.w};
#pragma unroll
        for (int q = 0; q < 4; q++) {
          acc[4*bq+q].x += ys4[q] * w[u].x;
          acc[4*bq+q].y += ys4[q] * w[u].y;
          acc[4*bq+q].z += ys4[q] * w[u].z;
          acc[4*bq+q].w += ys4[q] * w[u].w;
        }
      }
    }
    yr += 16;
  }

  // cross-warp tree reduction in smem
  float4* red = (float4*)smem;   // [16][128] float4
#pragma unroll
  for (int s = 4; s > 0; s >>= 1) {
    __syncthreads();
    if (wid >= s && wid < 2*s) {
      int slot = (wid - s) * 32 + lane;
#pragma unroll
      for (int b = 0; b < 16; b++) red[b*128 + slot] = acc[b];
    }
    __syncthreads();
    if (wid < s) {
      int slot = wid * 32 + lane;
#pragma unroll
      for (int b = 0; b < 16; b++) {
        float4 r = red[b*128 + slot];
        acc[b].x += r.x; acc[b].y += r.y; acc[b].z += r.z; acc[b].w += r.w;
      }
    }
  }

  if (wid == 0) {
#pragma unroll
    for (int b = 0; b < 16; b++)
      *(float4*)(part + (size_t)(blockIdx.y*16 + b) * N + c0) = acc[b];
  }
}

// =====================================================================
// Elementwise / small kernels
// =====================================================================
__global__ void zero_state()
{
  int idx = blockIdx.x * 256 + threadIdx.x;   // 16384
  g_h[idx] = 0.f;
  g_c[idx] = 0.f;
}

__global__ void enc_step_gates(int t, int nsplit, const int* __restrict__ enc_len)
{
  int idx = blockIdx.x * 256 + threadIdx.x;   // 16384
  int b = idx >> 10, j = idx & 1023;
  size_t zo = (size_t)(b*NT + t) * NG + j;
  float zi = g_zx_enc[zo], zj = g_zx_enc[zo+1024];
  float zf = g_zx_enc[zo+2048], zoo = g_zx_enc[zo+3072];
  for (int s = 0; s < nsplit; s++) {
    size_t po = (size_t)(s*16 + b) * NG + j;
    zi += g_zpart[po]; zj += g_zpart[po+1024];
    zf += g_zpart[po+2048]; zoo += g_zpart[po+3072];
  }
  float cn = g_c[idx] * sigm(zf + 1.f) + sigm(zi) * ftanh(zj);
  float hn = ftanh(cn) * sigm(zoo);
  bool valid = t < enc_len[b];
  if (valid) { g_h[idx] = hn; g_c[idx] = cn; }
  g_memory[(size_t)(b*NT + t) * NH + j] = valid ? hn : 0.f;
}

__global__ void dec_init()
{
  int idx = blockIdx.x * 256 + threadIdx.x;   // 32768
  int b = idx >> 11, j = idx & 2047;
  g_attn_h[idx] = (j < 1024) ? 0.f : g_h[b*NH + (j - 1024)];
}

__global__ void dec_step_gates(int t, int nsplit)
{
  int idx = blockIdx.x * 256 + threadIdx.x;   // 16384
  int b = idx >> 10, j = idx & 1023;
  size_t zo = (size_t)(b*NT + t) * NG + j;
  float zi = g_zx_dec[zo], zj = g_zx_dec[zo+1024];
  float zf = g_zx_dec[zo+2048], zoo = g_zx_dec[zo+3072];
  for (int s = 0; s < nsplit; s++) {
    size_t po = (size_t)(s*16 + b) * NG + j;
    zi += g_zpart[po]; zj += g_zpart[po+1024];
    zf += g_zpart[po+2048]; zoo += g_zpart[po+3072];
  }
  float cn = g_c[idx] * sigm(zf + 1.f) + sigm(zi) * ftanh(zj);
  float hn = ftanh(cn) * sigm(zoo);
  g_c[idx] = cn;
  g_attn_h[b*2*NH + NH + j] = hn;   // h slot for next step's recurrent input
  g_h_ctx[b*2*NH + j] = hn;         // h2 slot for query/attn gemms
}

// Fused: q-partial reduce + scores (tanh dot) + mask + softmax + context.
// One block per batch (16 blocks, 256 threads).
__global__ __launch_bounds__(256) void fused_attn(
    int nsplit, const int* __restrict__ enc_len, const float* __restrict__ v_att)
{
  __shared__ float sq[NH];
  __shared__ float sal[NT];
  int b = blockIdx.x;
  int tid = threadIdx.x, wid = tid >> 5, lane = tid & 31;

  for (int h = tid; h < NH; h += 256) {
    float q = 0.f;
    for (int s = 0; s < nsplit; s++) q += g_qpart[(size_t)(s*16 + b) * NH + h];
    sq[h] = q;
  }
  __syncthreads();

  int L = enc_len[b];
  for (int tt = wid; tt < NT; tt += 8) {
    const float* krow = g_keys + (size_t)(b*NT + tt) * NH;
    float acc = 0.f;
    for (int h0 = lane; h0 < NH; h0 += 32)
      acc += ftanh(krow[h0] + sq[h0]) * v_att[h0];
#pragma unroll
    for (int o = 16; o; o >>= 1) acc += __shfl_xor_sync(0xffffffffu, acc, o);
    if (lane == 0) sal[tt] = (tt < L) ? acc : -1e9f;
  }
  __syncthreads();

  float mx = -3e38f;
#pragma unroll
  for (int t2 = 0; t2 < NT; t2++) mx = fmaxf(mx, sal[t2]);
  __syncthreads();
  if (tid < NT) sal[tid] = expf(sal[tid] - mx);
  __syncthreads();
  float sum = 0.f;
#pragma unroll
  for (int t2 = 0; t2 < NT; t2++) sum += sal[t2];
  float inv = 1.f / sum;

  for (int h = tid; h < NH; h += 256) {
    const float* mb = g_memory + (size_t)b * NT * NH + h;
    float ctx = 0.f;
#pragma unroll 8
    for (int t2 = 0; t2 < NT; t2++) ctx += sal[t2] * mb[(size_t)t2 * NH];
    g_h_ctx[b*2*NH + NH + h] = ctx * inv;
  }
}

__global__ void attn_out(int t, int nsplit, const int* __restrict__ dec_len)
{
  int idx = blockIdx.x * 256 + threadIdx.x;   // 16384
  int b = idx >> 10, j = idx & 1023;
  float a = 0.f;
  for (int s = 0; s < nsplit; s++) a += g_apart[(size_t)(s*16 + b) * NH + j];
  g_attn_h[b*2*NH + j] = a;   // attn carry (unmasked)
  g_dec_out[(size_t)(b*NT + t) * NH + j] = (t >= dec_len[b]) ? 0.f : a;
}

// =====================================================================
// Host launch
// =====================================================================
extern "C" void kernel_launch(void* const* d_in, const int* in_sizes, int n_in,
                              void* d_out, int out_size)
{
  const int*   enc_in      = (const int*)d_in[0];
  const int*   dec_in      = (const int*)d_in[1];
  const int*   enc_len     = (const int*)d_in[2];
  const int*   dec_len     = (const int*)d_in[3];
  const float* embedding   = (const float*)d_in[4];
  const float* enc_kernel  = (const float*)d_in[5];
  const float* enc_bias    = (const float*)d_in[6];
  const float* dec_kernel  = (const float*)d_in[7];
  const float* dec_bias    = (const float*)d_in[8];
  const float* Wm          = (const float*)d_in[9];
  const float* Wq          = (const float*)d_in[10];
  const float* v_att       = (const float*)d_in[11];
  const float* attn_kernel = (const float*)d_in[12];
  const float* out_kernel  = (const float*)d_in[13];
  float* out = (float*)d_out;
  (void)in_sizes; (void)n_in; (void)out_size;

  float *zx_enc, *zx_dec, *mem, *keys, *dec_o, *zpart, *qpart, *apart, *hbuf, *attn_h, *h_ctx;
  cudaGetSymbolAddress((void**)&zx_enc, g_zx_enc);
  cudaGetSymbolAddress((void**)&zx_dec, g_zx_dec);
  cudaGetSymbolAddress((void**)&mem,    g_memory);
  cudaGetSymbolAddress((void**)&keys,   g_keys);
  cudaGetSymbolAddress((void**)&dec_o,  g_dec_out);
  cudaGetSymbolAddress((void**)&zpart,  g_zpart);
  cudaGetSymbolAddress((void**)&qpart,  g_qpart);
  cudaGetSymbolAddress((void**)&apart,  g_apart);
  cudaGetSymbolAddress((void**)&hbuf,   g_h);
  cudaGetSymbolAddress((void**)&attn_h, g_attn_h);
  cudaGetSymbolAddress((void**)&h_ctx,  g_h_ctx);

  const float* enc_Wrec = enc_kernel + (size_t)NE * NG;  // rows E..E+H-1
  const float* dec_Wrec = dec_kernel + (size_t)NE * NG;  // rows E..E+2H-1

  // init state
  zero_state<<<64, 256>>>();

  // Zx precompute: emb-gather GEMMs [1024 x 4096 x 256] with bias
  sgemm_nn<<<dim3(32, 8), 256>>>(NB*NT, NG, NE, embedding, enc_kernel, enc_bias, zx_enc, enc_in);
  sgemm_nn<<<dim3(32, 8), 256>>>(NB*NT, NG, NE, embedding, dec_kernel, dec_bias, zx_dec, dec_in);

  // ---- encoder ----
  for (int t = 0; t < NT; t++) {
    // h @ Wrec: K=1024, 16-way K-split -> 512 blocks (Kblk=64, kchunk=8)
    skinny_gemm<<<dim3(32, 16), 256>>>(hbuf, NH, enc_Wrec, NG, zpart, NG, NH);
    enc_step_gates<<<64, 256>>>(t, 16, enc_len);
  }

  // keys = memory @ Wm  [1024 x 1024 x 1024]
  sgemm_nn<<<dim3(8, 8), 256>>>(NB*NT, NH, NH, mem, Wm, nullptr, keys, nullptr);

  // ---- decoder ----
  dec_init<<<128, 256>>>();
  for (int t = 0; t < NT; t++) {
    // z = zx + [attn|h] @ dec_kernel[E:,:]   (K=2048, 32-way split -> 1024 blocks)
    skinny_gemm<<<dim3(32, 32), 256>>>(attn_h, 2*NH, dec_Wrec, NG, zpart, NG, 2*NH);
    dec_step_gates<<<64, 256>>>(t, 32);
    // query = h2 @ Wq   (K=1024, 32-way split -> 256 blocks, Kblk=32, kchunk=4)
    skinny_gemm<<<dim3(8, 32), 256>>>(h_ctx, 2*NH, Wq, NH, qpart, NH, NH);
    fused_attn<<<16, 256>>>(32, enc_len, v_att);
    // attn2 = [h2|context] @ attn_kernel   (K=2048, 32-way split -> 256 blocks)
    skinny_gemm<<<dim3(8, 32), 256>>>(h_ctx, 2*NH, attn_kernel, NH, apart, NH, 2*NH);
    attn_out<<<64, 256>>>(t, 32, dec_len);
  }

  // logits = dec_out @ out_kernel  [1024 x 32000 x 1024]
  sgemm_nn<<<dim3(250, 8), 256>>>(NB*NT, NV, NH, dec_o, out_kernel, nullptr, out, nullptr);
}

// round 7
// speedup vs baseline: 2.5519x; 1.8231x over previous
#include <cuda_runtime.h>
#include <math.h>

#define NB 16
#define NT 64
#define NV 32000
#define NE 256
#define NH 1024
#define NG 4096   // 4*H

// ---------------- device scratch (no allocs allowed) ----------------
__device__ float g_zx_enc[NB*NT*NG];
__device__ float g_zx_dec[NB*NT*NG];
__device__ float g_memory[NB*NT*NH];
__device__ float g_keys[NB*NT*NH];
__device__ float g_dec_out[NB*NT*NH];
__device__ float g_zpart[16*NB*NG];
__device__ float g_qpart[16*NB*NH];
__device__ float g_apart[16*NB*NH];
__device__ float g_h[NB*NH];
__device__ float g_c[NB*NH];
__device__ float g_attn_h[NB*2*NH];      // [attn | h] per batch (decoder recurrent input)
__device__ float g_h_ctx[NB*2*NH];       // [h2 | context] per batch
__device__ float g_scores[NB*NT];
__device__ int   g_rowidx[NB*NT];        // valid logits rows (gather into dec_out)
__device__ int   g_rowscat[NB*NT];       // scatter targets (-1 = skip/pad)
__device__ int   g_mpad;                 // padded valid-row count

__device__ __forceinline__ float sigm(float x){ return 1.f/(1.f + __expf(-x)); }
__device__ __forceinline__ float ftanh(float x){
  float a = fabsf(x);
  float e = __expf(-2.f * a);
  float t = (1.f - e) / (1.f + e);
  return copysignf(t, x);
}

__device__ __forceinline__ unsigned smem_u32(const void* p){
  return (unsigned)__cvta_generic_to_shared(p);
}
__device__ __forceinline__ void cp16(unsigned dst, const void* src){
  asm volatile("cp.async.cg.shared.global [%0], [%1], 16;\n" :: "r"(dst), "l"(src));
}
__device__ __forceinline__ void cp4(unsigned dst, const void* src){
  asm volatile("cp.async.ca.shared.global [%0], [%1], 4;\n" :: "r"(dst), "l"(src));
}
__device__ __forceinline__ void cp_commit(){
  asm volatile("cp.async.commit_group;\n");
}
__device__ __forceinline__ void cp_wait0(){
  asm volatile("cp.async.wait_group 0;\n");
}

// =====================================================================
// cp.async double-buffered SGEMM: C[M,N] = gatherA[M,K] @ W[K,N] (+bias).
// 128x128 tile, 256 threads, 8x8/thread, BK=8, 2 smem buffers, 1 sync/iter.
// Optional rowA gather, rowC scatter (-1 skips), device M bound (early exit).
// =====================================================================
__global__ __launch_bounds__(256, 2) void sgemm_db(
    int M, int N, int K,
    const float* __restrict__ A, const float* __restrict__ W,
    const float* __restrict__ bias, float* __restrict__ C,
    const int* __restrict__ rowA, const int* __restrict__ rowC,
    const int* __restrict__ mlimit)
{
  __shared__ float As[2][8][128];
  __shared__ float Bs[2][8][128];
  const int mbase = blockIdx.y * 128;
  if (mlimit && mbase >= *mlimit) return;
  const int nbase = blockIdx.x * 128;
  const int tid = threadIdx.x;
  const int tx = tid & 15;
  const int ty = tid >> 4;
  const int arow = tid >> 1;
  const int acol = (tid & 1) << 2;
  const int brow = tid >> 5;
  const int bcol = (tid & 31) << 2;
  int aIdx = mbase + arow;
  if (rowA) aIdx = rowA[aIdx];
  const float* Ap = A + (size_t)aIdx * K + acol;
  const float* Wp = W + (size_t)brow * N + nbase + bcol;

  unsigned sA[2][4], sB[2];
#pragma unroll
  for (int bf = 0; bf < 2; bf++) {
#pragma unroll
    for (int q = 0; q < 4; q++) sA[bf][q] = smem_u32(&As[bf][acol + q][arow]);
    sB[bf] = smem_u32(&Bs[bf][brow][bcol]);
  }

  float acc[8][8];
#pragma unroll
  for (int i = 0; i < 8; i++)
#pragma unroll
    for (int j = 0; j < 8; j++) acc[i][j] = 0.f;

  const int KT = K >> 3;
  // prologue: tile 0 -> buf 0
#pragma unroll
  for (int q = 0; q < 4; q++) cp4(sA[0][q], Ap + q);
  cp16(sB[0], Wp);
  cp_commit();

  for (int kt = 0; kt < KT; kt++) {
    cp_wait0();
    __syncthreads();
    if (kt + 1 < KT) {
      const float* Ap2 = Ap + (kt + 1) * 8;
      const float* Wp2 = Wp + (size_t)(kt + 1) * 8 * N;
      int nb = (kt + 1) & 1;
#pragma unroll
      for (int q = 0; q < 4; q++) cp4(sA[nb][q], Ap2 + q);
      cp16(sB[nb], Wp2);
      cp_commit();
    }
    int cb = kt & 1;
#pragma unroll
    for (int kk = 0; kk < 8; kk++) {
      float ar[8], br[8];
#pragma unroll
      for (int i = 0; i < 8; i++) ar[i] = As[cb][kk][ty*8 + i];
#pragma unroll
      for (int j = 0; j < 8; j++) br[j] = Bs[cb][kk][tx*8 + j];
#pragma unroll
      for (int i = 0; i < 8; i++)
#pragma unroll
        for (int j = 0; j < 8; j++) acc[i][j] += ar[i] * br[j];
    }
  }

  float bvals[8];
#pragma unroll
  for (int j = 0; j < 8; j++) bvals[j] = bias ? bias[nbase + tx*8 + j] : 0.f;
#pragma unroll
  for (int i = 0; i < 8; i++) {
    int crow = mbase + ty*8 + i;
    int cIdx = rowC ? rowC[crow] : crow;
    if (cIdx < 0) continue;
    float* cp = C + (size_t)cIdx * N + nbase + tx*8;
    float4 o0 = make_float4(acc[i][0]+bvals[0], acc[i][1]+bvals[1],
                            acc[i][2]+bvals[2], acc[i][3]+bvals[3]);
    float4 o1 = make_float4(acc[i][4]+bvals[4], acc[i][5]+bvals[5],
                            acc[i][6]+bvals[6], acc[i][7]+bvals[7]);
    *(float4*)(cp)     = o0;
    *(float4*)(cp + 4) = o1;
  }
}

// =====================================================================
// Skinny GEMM for M=16 recurrent matmuls, K-split, deterministic partials.
// (R5-proven: 4-row W prefetch.) grid=(N/128, KSPLIT), block=256.
// Kblk=K/gridDim.y; kchunk=Kblk/8 must be a multiple of 4.
// =====================================================================
__global__ __launch_bounds__(256, 2) void skinny_gemm(
    const float* __restrict__ y, int ystride,
    const float* __restrict__ W, int ldw,
    float* __restrict__ part, int N, int K)
{
  __shared__ __align__(16) float smem[8192];
  const int tid  = threadIdx.x;
  const int wid  = tid >> 5;
  const int lane = tid & 31;
  const int Kblk  = K / gridDim.y;
  const int kbase = blockIdx.y * Kblk;
  const int c0    = blockIdx.x * 128 + lane * 4;

  for (int idx = tid; idx < Kblk * 16; idx += 256) {
    int b = idx / Kblk;
    int kl = idx - b * Kblk;
    smem[kl*16 + b] = y[b * ystride + kbase + kl];
  }
  __syncthreads();

  const int kchunk = Kblk >> 3;
  const int ks0 = wid * kchunk;
  float4 acc[16];
#pragma unroll
  for (int b = 0; b < 16; b++) acc[b] = make_float4(0.f, 0.f, 0.f, 0.f);

  const float* Wp = W + (size_t)(kbase + ks0) * ldw + c0;
  const float4* yr = (const float4*)(smem + ks0 * 16);
  for (int k = 0; k < kchunk; k += 4) {
    float4 w[4];
#pragma unroll
    for (int u = 0; u < 4; u++) w[u] = *(const float4*)(Wp + (size_t)u * ldw);
    Wp += (size_t)4 * ldw;
#pragma unroll
    for (int u = 0; u < 4; u++) {
#pragma unroll
      for (int bq = 0; bq < 4; bq++) {
        float4 yv = yr[u*4 + bq];
        float ys4[4] = {yv.x, yv.y, yv.z, yv.w};
#pragma unroll
        for (int q = 0; q < 4; q++) {
          acc[4*bq+q].x += ys4[q] * w[u].x;
          acc[4*bq+q].y += ys4[q] * w[u].y;
          acc[4*bq+q].z += ys4[q] * w[u].z;
          acc[4*bq+q].w += ys4[q] * w[u].w;
        }
      }
    }
    yr += 16;
  }

  float4* red = (float4*)smem;
#pragma unroll
  for (int s = 4; s > 0; s >>= 1) {
    __syncthreads();
    if (wid >= s && wid < 2*s) {
      int slot = (wid - s) * 32 + lane;
#pragma unroll
      for (int b = 0; b < 16; b++) red[b*128 + slot] = acc[b];
    }
    __syncthreads();
    if (wid < s) {
      int slot = wid * 32 + lane;
#pragma unroll
      for (int b = 0; b < 16; b++) {
        float4 r = red[b*128 + slot];
        acc[b].x += r.x; acc[b].y += r.y; acc[b].z += r.z; acc[b].w += r.w;
      }
    }
  }

  if (wid == 0) {
#pragma unroll
    for (int b = 0; b < 16; b++)
      *(float4*)(part + (size_t)(blockIdx.y*16 + b) * N + c0) = acc[b];
  }
}

// =====================================================================
// Small kernels
// =====================================================================
__global__ void zero_state()
{
  int idx = blockIdx.x * 256 + threadIdx.x;
  g_h[idx] = 0.f;
  g_c[idx] = 0.f;
}

// Build compact valid-row list for the logits GEMM (rows t < dec_len[b]).
__global__ void build_rowlist(const int* __restrict__ dec_len)
{
  __shared__ int off[17];
  if (threadIdx.x == 0) {
    int s = 0; off[0] = 0;
    for (int b = 0; b < NB; b++) { s += dec_len[b]; off[b+1] = s; }
    g_mpad = (s + 127) & ~127;
  }
  __syncthreads();
  int nv = off[16];
  int mpad = (nv + 127) & ~127;
  for (int i = threadIdx.x; i < NB*NT; i += 256) {
    if (i < nv) {
      int b = 0;
      while (off[b+1] <= i) b++;
      int r = b*NT + (i - off[b]);
      g_rowidx[i] = r;
      g_rowscat[i] = r;
    } else if (i < mpad) {
      g_rowidx[i] = 0;
      g_rowscat[i] = -1;
    }
  }
}

// Zero logits rows for finished timesteps (d_out is poisoned).
__global__ void zero_invalid_logits(const int* __restrict__ dec_len, float* __restrict__ out)
{
  int row = blockIdx.y;
  int b = row >> 6, t = row & 63;
  if (t < dec_len[b]) return;
  int c = (blockIdx.x * 256 + threadIdx.x) * 4;
  if (c < NV) {
    float4 z = make_float4(0.f, 0.f, 0.f, 0.f);
    *(float4*)(out + (size_t)row * NV + c) = z;
  }
}

__global__ void enc_step_gates(int t, const int* __restrict__ enc_len)
{
  int idx = blockIdx.x * 256 + threadIdx.x;
  int b = idx >> 10, j = idx & 1023;
  size_t zo = (size_t)(b*NT + t) * NG + j;
  float zi = g_zx_enc[zo], zj = g_zx_enc[zo+1024];
  float zf = g_zx_enc[zo+2048], zoo = g_zx_enc[zo+3072];
#pragma unroll 4
  for (int s = 0; s < 16; s++) {
    size_t po = (size_t)(s*16 + b) * NG + j;
    zi += g_zpart[po]; zj += g_zpart[po+1024];
    zf += g_zpart[po+2048]; zoo += g_zpart[po+3072];
  }
  float cn = g_c[idx] * sigm(zf + 1.f) + sigm(zi) * ftanh(zj);
  float hn = ftanh(cn) * sigm(zoo);
  bool valid = t < enc_len[b];
  if (valid) { g_h[idx] = hn; g_c[idx] = cn; }
  g_memory[(size_t)(b*NT + t) * NH + j] = valid ? hn : 0.f;
}

__global__ void dec_init()
{
  int idx = blockIdx.x * 256 + threadIdx.x;
  int b = idx >> 11, j = idx & 2047;
  g_attn_h[idx] = (j < 1024) ? 0.f : g_h[b*NH + (j - 1024)];
}

__global__ void dec_step_gates(int t)
{
  int idx = blockIdx.x * 256 + threadIdx.x;
  int b = idx >> 10, j = idx & 1023;
  size_t zo = (size_t)(b*NT + t) * NG + j;
  float zi = g_zx_dec[zo], zj = g_zx_dec[zo+1024];
  float zf = g_zx_dec[zo+2048], zoo = g_zx_dec[zo+3072];
#pragma unroll 4
  for (int s = 0; s < 16; s++) {
    size_t po = (size_t)(s*16 + b) * NG + j;
    zi += g_zpart[po]; zj += g_zpart[po+1024];
    zf += g_zpart[po+2048]; zoo += g_zpart[po+3072];
  }
  float cn = g_c[idx] * sigm(zf + 1.f) + sigm(zi) * ftanh(zj);
  float hn = ftanh(cn) * sigm(zoo);
  g_c[idx] = cn;
  g_attn_h[b*2*NH + NH + j] = hn;
  g_h_ctx[b*2*NH + j] = hn;
}

__global__ __launch_bounds__(256) void attn_scores(
    const int* __restrict__ enc_len, const float* __restrict__ v_att)
{
  __shared__ float sq[NH];
  __shared__ float sv[NH];
  int b = blockIdx.x >> 3, tg = blockIdx.x & 7;
  int tid = threadIdx.x;
  for (int hh = tid; hh < NH; hh += 256) {
    float q = 0.f;
#pragma unroll 4
    for (int s = 0; s < 16; s++) q += g_qpart[(size_t)(s*16 + b) * NH + hh];
    sq[hh] = q;
    sv[hh] = v_att[hh];
  }
  __syncthreads();
  int wid = tid >> 5, lane = tid & 31;
  int tt = tg * 8 + wid;
  const float* krow = g_keys + (size_t)(b*NT + tt) * NH;
  float acc = 0.f;
  for (int h0 = lane; h0 < NH; h0 += 32)
    acc += ftanh(krow[h0] + sq[h0]) * sv[h0];
#pragma unroll
  for (int o = 16; o; o >>= 1) acc += __shfl_xor_sync(0xffffffffu, acc, o);
  if (lane == 0) g_scores[b*NT + tt] = (tt < enc_len[b]) ? acc : -1e9f;
}

__global__ __launch_bounds__(256) void softmax_ctx()
{
  __shared__ float sal[NT];
  int b = blockIdx.x >> 2, hc = blockIdx.x & 3;
  int tid = threadIdx.x;
  if (tid < NT) sal[tid] = g_scores[b*NT + tid];
  __syncthreads();
  float mx = -3e38f;
#pragma unroll
  for (int t2 = 0; t2 < NT; t2++) mx = fmaxf(mx, sal[t2]);
  __syncthreads();
  if (tid < NT) sal[tid] = __expf(sal[tid] - mx);
  __syncthreads();
  float sum = 0.f;
#pragma unroll
  for (int t2 = 0; t2 < NT; t2++) sum += sal[t2];
  float inv = 1.f / sum;
  int h = hc * 256 + tid;
  const float* mb = g_memory + (size_t)b * NT * NH + h;
  float ctx = 0.f;
#pragma unroll 8
  for (int t2 = 0; t2 < NT; t2++) ctx += sal[t2] * mb[(size_t)t2 * NH];
  g_h_ctx[b*2*NH + NH + h] = ctx * inv;
}

__global__ void attn_out(int t, const int* __restrict__ dec_len)
{
  int idx = blockIdx.x * 256 + threadIdx.x;
  int b = idx >> 10, j = idx & 1023;
  float a = 0.f;
#pragma unroll 4
  for (int s = 0; s < 16; s++) a += g_apart[(size_t)(s*16 + b) * NH + j];
  g_attn_h[b*2*NH + j] = a;
  g_dec_out[(size_t)(b*NT + t) * NH + j] = (t >= dec_len[b]) ? 0.f : a;
}

// =====================================================================
// Host launch
// =====================================================================
extern "C" void kernel_launch(void* const* d_in, const int* in_sizes, int n_in,
                              void* d_out, int out_size)
{
  const int*   enc_in      = (const int*)d_in[0];
  const int*   dec_in      = (const int*)d_in[1];
  const int*   enc_len     = (const int*)d_in[2];
  const int*   dec_len     = (const int*)d_in[3];
  const float* embedding   = (const float*)d_in[4];
  const float* enc_kernel  = (const float*)d_in[5];
  const float* enc_bias    = (const float*)d_in[6];
  const float* dec_kernel  = (const float*)d_in[7];
  const float* dec_bias    = (const float*)d_in[8];
  const float* Wm          = (const float*)d_in[9];
  const float* Wq          = (const float*)d_in[10];
  const float* v_att       = (const float*)d_in[11];
  const float* attn_kernel = (const float*)d_in[12];
  const float* out_kernel  = (const float*)d_in[13];
  float* out = (float*)d_out;
  (void)in_sizes; (void)n_in; (void)out_size;

  float *zx_enc, *zx_dec, *mem, *keys, *dec_o, *zpart, *qpart, *apart, *hbuf, *attn_h, *h_ctx;
  int *rowidx, *rowscat, *mpad;
  cudaGetSymbolAddress((void**)&zx_enc, g_zx_enc);
  cudaGetSymbolAddress((void**)&zx_dec, g_zx_dec);
  cudaGetSymbolAddress((void**)&mem,    g_memory);
  cudaGetSymbolAddress((void**)&keys,   g_keys);
  cudaGetSymbolAddress((void**)&dec_o,  g_dec_out);
  cudaGetSymbolAddress((void**)&zpart,  g_zpart);
  cudaGetSymbolAddress((void**)&qpart,  g_qpart);
  cudaGetSymbolAddress((void**)&apart,  g_apart);
  cudaGetSymbolAddress((void**)&hbuf,   g_h);
  cudaGetSymbolAddress((void**)&attn_h, g_attn_h);
  cudaGetSymbolAddress((void**)&h_ctx,  g_h_ctx);
  cudaGetSymbolAddress((void**)&rowidx, g_rowidx);
  cudaGetSymbolAddress((void**)&rowscat,g_rowscat);
  cudaGetSymbolAddress((void**)&mpad,   g_mpad);

  const float* enc_Wrec = enc_kernel + (size_t)NE * NG;
  const float* dec_Wrec = dec_kernel + (size_t)NE * NG;

  zero_state<<<64, 256>>>();
  build_rowlist<<<1, 256>>>(dec_len);
  zero_invalid_logits<<<dim3(32, 1024), 256>>>(dec_len, out);

  // Zx precompute: emb-gather GEMMs [1024 x 4096 x 256] with bias
  sgemm_db<<<dim3(32, 8), 256>>>(NB*NT, NG, NE, embedding, enc_kernel, enc_bias,
                                 zx_enc, enc_in, nullptr, nullptr);
  sgemm_db<<<dim3(32, 8), 256>>>(NB*NT, NG, NE, embedding, dec_kernel, dec_bias,
                                 zx_dec, dec_in, nullptr, nullptr);

  // ---- encoder ----
  for (int t = 0; t < NT; t++) {
    skinny_gemm<<<dim3(32, 16), 256>>>(hbuf, NH, enc_Wrec, NG, zpart, NG, NH);
    enc_step_gates<<<64, 256>>>(t, enc_len);
  }

  // keys = memory @ Wm  [1024 x 1024 x 1024]
  sgemm_db<<<dim3(8, 8), 256>>>(NB*NT, NH, NH, mem, Wm, nullptr, keys,
                                nullptr, nullptr, nullptr);

  // ---- decoder ----
  dec_init<<<128, 256>>>();
  for (int t = 0; t < NT; t++) {
    skinny_gemm<<<dim3(32, 16), 256>>>(attn_h, 2*NH, dec_Wrec, NG, zpart, NG, 2*NH);
    dec_step_gates<<<64, 256>>>(t);
    skinny_gemm<<<dim3(8, 16), 256>>>(h_ctx, 2*NH, Wq, NH, qpart, NH, NH);
    attn_scores<<<128, 256>>>(enc_len, v_att);
    softmax_ctx<<<64, 256>>>();
    skinny_gemm<<<dim3(8, 16), 256>>>(h_ctx, 2*NH, attn_kernel, NH, apart, NH, 2*NH);
    attn_out<<<64, 256>>>(t, dec_len);
  }

  // logits = dec_out[valid rows] @ out_kernel, scattered; invalid rows zero-filled
  sgemm_db<<<dim3(250, 8), 256>>>(NB*NT, NV, NH, dec_o, out_kernel, nullptr, out,
                                  rowidx, rowscat, mpad);
}

// round 10
// speedup vs baseline: 2.9525x; 1.1570x over previous
#include <cuda_runtime.h>
#include <cuda_bf16.h>
#include <stdint.h>
#include <math.h>
#include <string.h>

#define NB 16
#define NT 64
#define NV 32000
#define NE 256
#define NH 1024
#define NG 4096   // 4*H

// ---------------- device scratch (no allocs allowed) ----------------
__device__ float g_zx_enc[NB*NT*NG];
__device__ float g_zx_dec[NB*NT*NG];
__device__ float g_memory[NB*NT*NH];
__device__ float g_keys[NB*NT*NH];
__device__ float g_dec_out[NB*NT*NH];
__device__ float g_zpart[16*NB*NG];
__device__ float g_qpart[16*NB*NH];
__device__ float g_apart[16*NB*NH];
__device__ float g_h[NB*NH];
__device__ float g_c[NB*NH];
__device__ float g_attn_h[NB*2*NH];      // [attn | h] per batch (decoder recurrent input)
__device__ float g_h_ctx[NB*2*NH];       // [h2 | context] per batch
__device__ float g_scores[NB*NT];
__device__ int   g_rowidx[NB*NT];        // valid logits rows (gather into dec_out)
__device__ int   g_rowscat[NB*NT];       // scatter targets (-1 = skip/pad)
__device__ int   g_mpad;                 // padded valid-row count
// bf16 hi/lo split operands for the tensor-core logits GEMM
__device__ __nv_bfloat16 g_Whi[(size_t)NH*NV];
__device__ __nv_bfloat16 g_Wlo[(size_t)NH*NV];
__device__ __nv_bfloat16 g_Ahi[(size_t)NB*NT*NH];
__device__ __nv_bfloat16 g_Alo[(size_t)NB*NT*NH];

__device__ __forceinline__ float sigm(float x){ return 1.f/(1.f + __expf(-x)); }
__device__ __forceinline__ float ftanh(float x){
  float a = fabsf(x);
  float e = __expf(-2.f * a);
  float t = (1.f - e) / (1.f + e);
  return copysignf(t, x);
}

__device__ __forceinline__ unsigned smem_u32(const void* p){
  return (unsigned)__cvta_generic_to_shared(p);
}
__device__ __forceinline__ void cp16(unsigned dst, const void* src){
  asm volatile("cp.async.cg.shared.global [%0], [%1], 16;\n" :: "r"(dst), "l"(src));
}
__device__ __forceinline__ void cp4(unsigned dst, const void* src){
  asm volatile("cp.async.ca.shared.global [%0], [%1], 4;\n" :: "r"(dst), "l"(src));
}
__device__ __forceinline__ void cp_commit(){
  asm volatile("cp.async.commit_group;\n");
}
__device__ __forceinline__ void cp_wait0(){
  asm volatile("cp.async.wait_group 0;\n");
}

// ---------------- mma.sync helpers (baseline PTX, works on sm_103) ----------
__device__ __forceinline__ void ldm4(unsigned* r, unsigned a){
  asm volatile("ldmatrix.sync.aligned.m8n8.x4.shared.b16 {%0,%1,%2,%3}, [%4];"
    : "=r"(r[0]), "=r"(r[1]), "=r"(r[2]), "=r"(r[3]) : "r"(a));
}
__device__ __forceinline__ void ldm4t(unsigned* r, unsigned a){
  asm volatile("ldmatrix.sync.aligned.m8n8.x4.trans.shared.b16 {%0,%1,%2,%3}, [%4];"
    : "=r"(r[0]), "=r"(r[1]), "=r"(r[2]), "=r"(r[3]) : "r"(a));
}
__device__ __forceinline__ void mma_bf16(float* c, const unsigned* a,
                                         unsigned b0, unsigned b1){
  asm volatile(
    "mma.sync.aligned.m16n8k16.row.col.f32.bf16.bf16.f32 "
    "{%0,%1,%2,%3}, {%4,%5,%6,%7}, {%8,%9}, {%0,%1,%2,%3};"
    : "+f"(c[0]), "+f"(c[1]), "+f"(c[2]), "+f"(c[3])
    : "r"(a[0]), "r"(a[1]), "r"(a[2]), "r"(a[3]), "r"(b0), "r"(b1));
}
__device__ __forceinline__ unsigned pkbf2(__nv_bfloat16 a, __nv_bfloat16 b){
  __nv_bfloat162 t;
  t.x = a;
  t.y = b;
  unsigned u;
  memcpy(&u, &t, 4);
  return u;
}

// =====================================================================
// fp32 -> (hi, lo) bf16 split conversions (once per launch)
// =====================================================================
__global__ void conv_W(const float* __restrict__ W)
{
  size_t i = ((size_t)blockIdx.x * 256 + threadIdx.x) * 4;   // grid 32000 -> exactly NH*NV
  float4 v = *(const float4*)(W + i);
  __nv_bfloat16 h0 = __float2bfloat16_rn(v.x);
  __nv_bfloat16 h1 = __float2bfloat16_rn(v.y);
  __nv_bfloat16 h2 = __float2bfloat16_rn(v.z);
  __nv_bfloat16 h3 = __float2bfloat16_rn(v.w);
  __nv_bfloat16 l0 = __float2bfloat16_rn(v.x - __bfloat162float(h0));
  __nv_bfloat16 l1 = __float2bfloat16_rn(v.y - __bfloat162float(h1));
  __nv_bfloat16 l2 = __float2bfloat16_rn(v.z - __bfloat162float(h2));
  __nv_bfloat16 l3 = __float2bfloat16_rn(v.w - __bfloat162float(h3));
  *(uint2*)(g_Whi + i) = make_uint2(pkbf2(h0, h1), pkbf2(h2, h3));
  *(uint2*)(g_Wlo + i) = make_uint2(pkbf2(l0, l1), pkbf2(l2, l3));
}

__global__ void conv_A()
{
  size_t i = ((size_t)blockIdx.x * 256 + threadIdx.x) * 4;   // grid 1024 -> 1024*1024
  int row = (int)(i >> 10);
  int k = (int)(i & 1023);
  int src = g_rowidx[row];
  float4 v = *(const float4*)(g_dec_out + (size_t)src * NH + k);
  __nv_bfloat16 h0 = __float2bfloat16_rn(v.x);
  __nv_bfloat16 h1 = __float2bfloat16_rn(v.y);
  __nv_bfloat16 h2 = __float2bfloat16_rn(v.z);
  __nv_bfloat16 h3 = __float2bfloat16_rn(v.w);
  __nv_bfloat16 l0 = __float2bfloat16_rn(v.x - __bfloat162float(h0));
  __nv_bfloat16 l1 = __float2bfloat16_rn(v.y - __bfloat162float(h1));
  __nv_bfloat16 l2 = __float2bfloat16_rn(v.z - __bfloat162float(h2));
  __nv_bfloat16 l3 = __float2bfloat16_rn(v.w - __bfloat162float(h3));
  *(uint2*)(g_Ahi + i) = make_uint2(pkbf2(h0, h1), pkbf2(h2, h3));
  *(uint2*)(g_Alo + i) = make_uint2(pkbf2(l0, l1), pkbf2(l2, l3));
}

// =====================================================================
// Logits GEMM via mma.sync bf16 (hi/lo split, fp32 accum).
// C[rowC[m]][n] = sum_k A[m][k] * W[k][n] over compacted rows.
// CTA tile 128(m) x 64(n), 256 threads = 8 warps (4m x 2n),
// warp tile 32x32 = 2 m16 x 4 n8 fragments. K chunk 32, double-buffered.
// smem strides: A 80 B/row, B 144 B/row (conflict-free ldmatrix).
// Dynamic smem = 2*2*10240 + 2*2*4608 = 59392 bytes.
// =====================================================================
__global__ __launch_bounds__(256, 2) void logits_mma(
    const __nv_bfloat16* __restrict__ Ahi, const __nv_bfloat16* __restrict__ Alo,
    const __nv_bfloat16* __restrict__ Whi, const __nv_bfloat16* __restrict__ Wlo,
    float* __restrict__ C, const int* __restrict__ rowC,
    const int* __restrict__ mlimit)
{
  extern __shared__ __align__(128) char sm[];
  const int mbase = blockIdx.y * 128;
  if (mbase >= *mlimit) return;
  const int n0 = blockIdx.x * 64;

  const unsigned sb = smem_u32(sm);
  const int tid = threadIdx.x;
  const int lane = tid & 31;
  const int wid = tid >> 5;
  const int wm = wid & 3;        // warp m position (0..3)
  const int wn = wid >> 2;       // warp n position (0..1)

  float acc[2][4][4];
#pragma unroll
  for (int mt = 0; mt < 2; mt++)
#pragma unroll
    for (int nt = 0; nt < 4; nt++)
#pragma unroll
      for (int e = 0; e < 4; e++) acc[mt][nt][e] = 0.f;

  // buffer offsets (bytes from sb)
  //   A buf b: hi at b*20480, lo at b*20480 + 10240   (128 rows x 80 B)
  //   B buf b: hi at 40960 + b*9216, lo +4608          (32 rows x 144 B)

  // ---- prologue: fill buffer 0 (kc = 0) ----
#pragma unroll
  for (int rep = 0; rep < 2; rep++) {
    int i = tid + rep * 256;         // 512 A-slots
    int m = i >> 2;
    int q = i & 3;
    unsigned dst = sb + m*80 + q*16;
    cp16(dst,        Ahi + (size_t)(mbase + m) * NH + q*8);
    cp16(dst + 10240, Alo + (size_t)(mbase + m) * NH + q*8);
  }
  {
    int kr = tid >> 3;
    int q = tid & 7;
    unsigned dst = sb + 40960 + kr*144 + q*16;
    cp16(dst,        Whi + (size_t)kr * NV + n0 + q*8);
    cp16(dst + 4608, Wlo + (size_t)kr * NV + n0 + q*8);
  }
  cp_commit();

  for (int kt = 0; kt < 32; kt++) {
    cp_wait0();
    __syncthreads();
    if (kt + 1 < 32) {
      const int kc = (kt + 1) * 32;
      const int nb = (kt + 1) & 1;
#pragma unroll
      for (int rep = 0; rep < 2; rep++) {
        int i = tid + rep * 256;
        int m = i >> 2;
        int q = i & 3;
        unsigned dst = sb + nb*20480 + m*80 + q*16;
        cp16(dst,         Ahi + (size_t)(mbase + m) * NH + kc + q*8);
        cp16(dst + 10240, Alo + (size_t)(mbase + m) * NH + kc + q*8);
      }
      {
        int kr = tid >> 3;
        int q = tid & 7;
        unsigned dst = sb + 40960 + nb*9216 + kr*144 + q*16;
        cp16(dst,        Whi + (size_t)(kc + kr) * NV + n0 + q*8);
        cp16(dst + 4608, Wlo + (size_t)(kc + kr) * NV + n0 + q*8);
      }
      cp_commit();
    }

    const int buf = kt & 1;
    const unsigned aB = sb + buf*20480;
    const unsigned bB = sb + 40960 + buf*9216;

#pragma unroll
    for (int ks = 0; ks < 2; ks++) {
      unsigned aH[2][4], aL[2][4], bH[2][4], bL[2][4];
      // A fragments: ldmatrix x4, addr = row (lane%16), k-half (lane/16)
      const int ar = lane & 15;
      const int ak = (lane >> 4) * 8;
#pragma unroll
      for (int mt = 0; mt < 2; mt++) {
        unsigned ad = aB + (unsigned)((wm*32 + mt*16 + ar)*80 + (ks*16 + ak)*2);
        ldm4(aH[mt], ad);
        ldm4(aL[mt], ad + 10240);
      }
      // B fragments: ldmatrix x4 trans from [k][n] smem
      const int krow = ks*16 + ((lane >> 3) & 1)*8 + (lane & 7);
#pragma unroll
      for (int p = 0; p < 2; p++) {
        int nc = wn*32 + p*16 + (lane >> 4)*8;
        unsigned bd = bB + (unsigned)(krow*144 + nc*2);
        ldm4t(bH[p], bd);
        ldm4t(bL[p], bd + 4608);
      }
#pragma unroll
      for (int mt = 0; mt < 2; mt++)
#pragma unroll
        for (int p = 0; p < 2; p++)
#pragma unroll
          for (int j = 0; j < 2; j++) {
            int nt = p*2 + j;
            mma_bf16(acc[mt][nt], aH[mt], bH[p][2*j], bH[p][2*j+1]);
            mma_bf16(acc[mt][nt], aH[mt], bL[p][2*j], bL[p][2*j+1]);
            mma_bf16(acc[mt][nt], aL[mt], bH[p][2*j], bH[p][2*j+1]);
          }
    }
  }

  // ---- store: acc mapping: c0,c1 -> row g, cols c0n,c0n+1; c2,c3 -> row g+8 ----
  const int g = lane >> 2;
  const int c0n = (lane & 3) * 2;
#pragma unroll
  for (int mt = 0; mt < 2; mt++) {
    int r0 = wm*32 + mt*16 + g;
    int sc0 = rowC[mbase + r0];
    int sc1 = rowC[mbase + r0 + 8];
#pragma unroll
    for (int nt = 0; nt < 4; nt++) {
      int col = n0 + wn*32 + nt*8 + c0n;
      if (sc0 >= 0) {
        float2 v0 = make_float2(acc[mt][nt][0], acc[mt][nt][1]);
        *(float2*)(C + (size_t)sc0 * NV + col) = v0;
      }
      if (sc1 >= 0) {
        float2 v1 = make_float2(acc[mt][nt][2], acc[mt][nt][3]);
        *(float2*)(C + (size_t)sc1 * NV + col) = v1;
      }
    }
  }
}

// =====================================================================
// cp.async double-buffered SGEMM (R7-proven): C = gatherA @ W (+bias).
// =====================================================================
__global__ __launch_bounds__(256, 2) void sgemm_db(
    int M, int N, int K,
    const float* __restrict__ A, const float* __restrict__ W,
    const float* __restrict__ bias, float* __restrict__ C,
    const int* __restrict__ rowA, const int* __restrict__ rowC,
    const int* __restrict__ mlimit)
{
  __shared__ float As[2][8][128];
  __shared__ float Bs[2][8][128];
  const int mbase = blockIdx.y * 128;
  if (mlimit && mbase >= *mlimit) return;
  const int nbase = blockIdx.x * 128;
  const int tid = threadIdx.x;
  const int tx = tid & 15;
  const int ty = tid >> 4;
  const int arow = tid >> 1;
  const int acol = (tid & 1) << 2;
  const int brow = tid >> 5;
  const int bcol = (tid & 31) << 2;
  int aIdx = mbase + arow;
  if (rowA) aIdx = rowA[aIdx];
  const float* Ap = A + (size_t)aIdx * K + acol;
  const float* Wp = W + (size_t)brow * N + nbase + bcol;

  unsigned sA[2][4];
  unsigned sB[2];
#pragma unroll
  for (int bf = 0; bf < 2; bf++) {
#pragma unroll
    for (int qq = 0; qq < 4; qq++) sA[bf][qq] = smem_u32(&As[bf][acol + qq][arow]);
    sB[bf] = smem_u32(&Bs[bf][brow][bcol]);
  }

  float acc[8][8];
#pragma unroll
  for (int i = 0; i < 8; i++)
#pragma unroll
    for (int j = 0; j < 8; j++) acc[i][j] = 0.f;

  const int KT = K >> 3;
#pragma unroll
  for (int qq = 0; qq < 4; qq++) cp4(sA[0][qq], Ap + qq);
  cp16(sB[0], Wp);
  cp_commit();

  for (int kt = 0; kt < KT; kt++) {
    cp_wait0();
    __syncthreads();
    if (kt + 1 < KT) {
      const float* Ap2 = Ap + (kt + 1) * 8;
      const float* Wp2 = Wp + (size_t)(kt + 1) * 8 * N;
      int nb = (kt + 1) & 1;
#pragma unroll
      for (int qq = 0; qq < 4; qq++) cp4(sA[nb][qq], Ap2 + qq);
      cp16(sB[nb], Wp2);
      cp_commit();
    }
    int cb = kt & 1;
#pragma unroll
    for (int kk = 0; kk < 8; kk++) {
      float ar[8];
      float br[8];
#pragma unroll
      for (int i = 0; i < 8; i++) ar[i] = As[cb][kk][ty*8 + i];
#pragma unroll
      for (int j = 0; j < 8; j++) br[j] = Bs[cb][kk][tx*8 + j];
#pragma unroll
      for (int i = 0; i < 8; i++)
#pragma unroll
        for (int j = 0; j < 8; j++) acc[i][j] += ar[i] * br[j];
    }
  }

  float bvals[8];
#pragma unroll
  for (int j = 0; j < 8; j++) bvals[j] = bias ? bias[nbase + tx*8 + j] : 0.f;
#pragma unroll
  for (int i = 0; i < 8; i++) {
    int crow = mbase + ty*8 + i;
    int cIdx = rowC ? rowC[crow] : crow;
    if (cIdx < 0) continue;
    float* cp = C + (size_t)cIdx * N + nbase + tx*8;
    float4 o0 = make_float4(acc[i][0]+bvals[0], acc[i][1]+bvals[1],
                            acc[i][2]+bvals[2], acc[i][3]+bvals[3]);
    float4 o1 = make_float4(acc[i][4]+bvals[4], acc[i][5]+bvals[5],
                            acc[i][6]+bvals[6], acc[i][7]+bvals[7]);
    *(float4*)(cp)     = o0;
    *(float4*)(cp + 4) = o1;
  }
}

// =====================================================================
// Skinny GEMM (R7-proven)
// =====================================================================
__global__ __launch_bounds__(256, 2) void skinny_gemm(
    const float* __restrict__ y, int ystride,
    const float* __restrict__ W, int ldw,
    float* __restrict__ part, int N, int K)
{
  __shared__ __align__(16) float smem[8192];
  const int tid  = threadIdx.x;
  const int wid  = tid >> 5;
  const int lane = tid & 31;
  const int Kblk  = K / gridDim.y;
  const int kbase = blockIdx.y * Kblk;
  const int c0    = blockIdx.x * 128 + lane * 4;

  for (int idx = tid; idx < Kblk * 16; idx += 256) {
    int b = idx / Kblk;
    int kl = idx - b * Kblk;
    smem[kl*16 + b] = y[b * ystride + kbase + kl];
  }
  __syncthreads();

  const int kchunk = Kblk >> 3;
  const int ks0 = wid * kchunk;
  float4 acc[16];
#pragma unroll
  for (int b = 0; b < 16; b++) acc[b] = make_float4(0.f, 0.f, 0.f, 0.f);

  const float* Wp = W + (size_t)(kbase + ks0) * ldw + c0;
  const float4* yr = (const float4*)(smem + ks0 * 16);
  for (int k = 0; k < kchunk; k += 4) {
    float4 w[4];
#pragma unroll
    for (int u = 0; u < 4; u++) w[u] = *(const float4*)(Wp + (size_t)u * ldw);
    Wp += (size_t)4 * ldw;
#pragma unroll
    for (int u = 0; u < 4; u++) {
#pragma unroll
      for (int bq = 0; bq < 4; bq++) {
        float4 yv = yr[u*4 + bq];
        float ys4[4] = {yv.x, yv.y, yv.z, yv.w};
#pragma unroll
        for (int qq = 0; qq < 4; qq++) {
          acc[4*bq+qq].x += ys4[qq] * w[u].x;
          acc[4*bq+qq].y += ys4[qq] * w[u].y;
          acc[4*bq+qq].z += ys4[qq] * w[u].z;
          acc[4*bq+qq].w += ys4[qq] * w[u].w;
        }
      }
    }
    yr += 16;
  }

  float4* red = (float4*)smem;
#pragma unroll
  for (int s = 4; s > 0; s >>= 1) {
    __syncthreads();
    if (wid >= s && wid < 2*s) {
      int slot = (wid - s) * 32 + lane;
#pragma unroll
      for (int b = 0; b < 16; b++) red[b*128 + slot] = acc[b];
    }
    __syncthreads();
    if (wid < s) {
      int slot = wid * 32 + lane;
#pragma unroll
      for (int b = 0; b < 16; b++) {
        float4 r = red[b*128 + slot];
        acc[b].x += r.x;
        acc[b].y += r.y;
        acc[b].z += r.z;
        acc[b].w += r.w;
      }
    }
  }

  if (wid == 0) {
#pragma unroll
    for (int b = 0; b < 16; b++)
      *(float4*)(part + (size_t)(blockIdx.y*16 + b) * N + c0) = acc[b];
  }
}

// =====================================================================
// Small kernels (R7-proven)
// =====================================================================
__global__ void zero_state()
{
  int idx = blockIdx.x * 256 + threadIdx.x;
  g_h[idx] = 0.f;
  g_c[idx] = 0.f;
}

__global__ void build_rowlist(const int* __restrict__ dec_len)
{
  __shared__ int off[17];
  if (threadIdx.x == 0) {
    int s = 0;
    off[0] = 0;
    for (int b = 0; b < NB; b++) {
      s += dec_len[b];
      off[b+1] = s;
    }
    g_mpad = (s + 127) & ~127;
  }
  __syncthreads();
  int nv = off[16];
  int mpad = (nv + 127) & ~127;
  for (int i = threadIdx.x; i < NB*NT; i += 256) {
    if (i < nv) {
      int b = 0;
      while (off[b+1] <= i) b++;
      int r = b*NT + (i - off[b]);
      g_rowidx[i] = r;
      g_rowscat[i] = r;
    } else if (i < mpad) {
      g_rowidx[i] = 0;
      g_rowscat[i] = -1;
    }
  }
}

__global__ void zero_invalid_logits(const int* __restrict__ dec_len, float* __restrict__ out)
{
  int row = blockIdx.y;
  int b = row >> 6;
  int t = row & 63;
  if (t < dec_len[b]) return;
  int c = (blockIdx.x * 256 + threadIdx.x) * 4;
  if (c < NV) {
    float4 z = make_float4(0.f, 0.f, 0.f, 0.f);
    *(float4*)(out + (size_t)row * NV + c) = z;
  }
}

__global__ void enc_step_gates(int t, const int* __restrict__ enc_len)
{
  int idx = blockIdx.x * 256 + threadIdx.x;
  int b = idx >> 10;
  int j = idx & 1023;
  size_t zo = (size_t)(b*NT + t) * NG + j;
  float zi = g_zx_enc[zo];
  float zj = g_zx_enc[zo+1024];
  float zf = g_zx_enc[zo+2048];
  float zoo = g_zx_enc[zo+3072];
#pragma unroll 4
  for (int s = 0; s < 16; s++) {
    size_t po = (size_t)(s*16 + b) * NG + j;
    zi += g_zpart[po];
    zj += g_zpart[po+1024];
    zf += g_zpart[po+2048];
    zoo += g_zpart[po+3072];
  }
  float cn = g_c[idx] * sigm(zf + 1.f) + sigm(zi) * ftanh(zj);
  float hn = ftanh(cn) * sigm(zoo);
  bool valid = t < enc_len[b];
  if (valid) {
    g_h[idx] = hn;
    g_c[idx] = cn;
  }
  g_memory[(size_t)(b*NT + t) * NH + j] = valid ? hn : 0.f;
}

__global__ void dec_init()
{
  int idx = blockIdx.x * 256 + threadIdx.x;
  int b = idx >> 11;
  int j = idx & 2047;
  g_attn_h[idx] = (j < 1024) ? 0.f : g_h[b*NH + (j - 1024)];
}

__global__ void dec_step_gates(int t)
{
  int idx = blockIdx.x * 256 + threadIdx.x;
  int b = idx >> 10;
  int j = idx & 1023;
  size_t zo = (size_t)(b*NT + t) * NG + j;
  float zi = g_zx_dec[zo];
  float zj = g_zx_dec[zo+1024];
  float zf = g_zx_dec[zo+2048];
  float zoo = g_zx_dec[zo+3072];
#pragma unroll 4
  for (int s = 0; s < 16; s++) {
    size_t po = (size_t)(s*16 + b) * NG + j;
    zi += g_zpart[po];
    zj += g_zpart[po+1024];
    zf += g_zpart[po+2048];
    zoo += g_zpart[po+3072];
  }
  float cn = g_c[idx] * sigm(zf + 1.f) + sigm(zi) * ftanh(zj);
  float hn = ftanh(cn) * sigm(zoo);
  g_c[idx] = cn;
  g_attn_h[b*2*NH + NH + j] = hn;
  g_h_ctx[b*2*NH + j] = hn;
}

__global__ __launch_bounds__(256) void attn_scores(
    const int* __restrict__ enc_len, const float* __restrict__ v_att)
{
  __shared__ float sq[NH];
  __shared__ float sv[NH];
  int b = blockIdx.x >> 3;
  int tg = blockIdx.x & 7;
  int tid = threadIdx.x;
  for (int hh = tid; hh < NH; hh += 256) {
    float qv = 0.f;
#pragma unroll 4
    for (int s = 0; s < 16; s++) qv += g_qpart[(size_t)(s*16 + b) * NH + hh];
    sq[hh] = qv;
    sv[hh] = v_att[hh];
  }
  __syncthreads();
  int wid = tid >> 5;
  int lane = tid & 31;
  int tt = tg * 8 + wid;
  const float* krow = g_keys + (size_t)(b*NT + tt) * NH;
  float acc = 0.f;
  for (int h0 = lane; h0 < NH; h0 += 32)
    acc += ftanh(krow[h0] + sq[h0]) * sv[h0];
#pragma unroll
  for (int o = 16; o; o >>= 1) acc += __shfl_xor_sync(0xffffffffu, acc, o);
  if (lane == 0) g_scores[b*NT + tt] = (tt < enc_len[b]) ? acc : -1e9f;
}

__global__ __launch_bounds__(256) void softmax_ctx()
{
  __shared__ float sal[NT];
  int b = blockIdx.x >> 2;
  int hc = blockIdx.x & 3;
  int tid = threadIdx.x;
  if (tid < NT) sal[tid] = g_scores[b*NT + tid];
  __syncthreads();
  float mx = -3e38f;
#pragma unroll
  for (int t2 = 0; t2 < NT; t2++) mx = fmaxf(mx, sal[t2]);
  __syncthreads();
  if (tid < NT) sal[tid] = __expf(sal[tid] - mx);
  __syncthreads();
  float sum = 0.f;
#pragma unroll
  for (int t2 = 0; t2 < NT; t2++) sum += sal[t2];
  float inv = 1.f / sum;
  int h = hc * 256 + tid;
  const float* mb = g_memory + (size_t)b * NT * NH + h;
  float ctx = 0.f;
#pragma unroll 8
  for (int t2 = 0; t2 < NT; t2++) ctx += sal[t2] * mb[(size_t)t2 * NH];
  g_h_ctx[b*2*NH + NH + h] = ctx * inv;
}

__global__ void attn_out(int t, const int* __restrict__ dec_len)
{
  int idx = blockIdx.x * 256 + threadIdx.x;
  int b = idx >> 10;
  int j = idx & 1023;
  float a = 0.f;
#pragma unroll 4
  for (int s = 0; s < 16; s++) a += g_apart[(size_t)(s*16 + b) * NH + j];
  g_attn_h[b*2*NH + j] = a;
  g_dec_out[(size_t)(b*NT + t) * NH + j] = (t >= dec_len[b]) ? 0.f : a;
}

// =====================================================================
// Host launch
// =====================================================================
extern "C" void kernel_launch(void* const* d_in, const int* in_sizes, int n_in,
                              void* d_out, int out_size)
{
  const int*   enc_in      = (const int*)d_in[0];
  const int*   dec_in      = (const int*)d_in[1];
  const int*   enc_len     = (const int*)d_in[2];
  const int*   dec_len     = (const int*)d_in[3];
  const float* embedding   = (const float*)d_in[4];
  const float* enc_kernel  = (const float*)d_in[5];
  const float* enc_bias    = (const float*)d_in[6];
  const float* dec_kernel  = (const float*)d_in[7];
  const float* dec_bias    = (const float*)d_in[8];
  const float* Wm          = (const float*)d_in[9];
  const float* Wq          = (const float*)d_in[10];
  const float* v_att       = (const float*)d_in[11];
  const float* attn_kernel = (const float*)d_in[12];
  const float* out_kernel  = (const float*)d_in[13];
  float* out = (float*)d_out;
  (void)in_sizes;
  (void)n_in;
  (void)out_size;

  float *zx_enc, *zx_dec, *mem, *keys, *dec_o, *zpart, *qpart, *apart;
  float *hbuf, *attn_h, *h_ctx;
  int *rowidx, *rowscat, *mpad;
  __nv_bfloat16 *whi, *wlo, *ahi, *alo;
  cudaGetSymbolAddress((void**)&zx_enc, g_zx_enc);
  cudaGetSymbolAddress((void**)&zx_dec, g_zx_dec);
  cudaGetSymbolAddress((void**)&mem,    g_memory);
  cudaGetSymbolAddress((void**)&keys,   g_keys);
  cudaGetSymbolAddress((void**)&dec_o,  g_dec_out);
  cudaGetSymbolAddress((void**)&zpart,  g_zpart);
  cudaGetSymbolAddress((void**)&qpart,  g_qpart);
  cudaGetSymbolAddress((void**)&apart,  g_apart);
  cudaGetSymbolAddress((void**)&hbuf,   g_h);
  cudaGetSymbolAddress((void**)&attn_h, g_attn_h);
  cudaGetSymbolAddress((void**)&h_ctx,  g_h_ctx);
  cudaGetSymbolAddress((void**)&rowidx, g_rowidx);
  cudaGetSymbolAddress((void**)&rowscat, g_rowscat);
  cudaGetSymbolAddress((void**)&mpad,   g_mpad);
  cudaGetSymbolAddress((void**)&whi,    g_Whi);
  cudaGetSymbolAddress((void**)&wlo,    g_Wlo);
  cudaGetSymbolAddress((void**)&ahi,    g_Ahi);
  cudaGetSymbolAddress((void**)&alo,    g_Alo);

  const float* enc_Wrec = enc_kernel + (size_t)NE * NG;
  const float* dec_Wrec = dec_kernel + (size_t)NE * NG;

  const int LOGITS_SMEM = 2*2*10240 + 2*2*4608;  // 59392
  cudaFuncSetAttribute(logits_mma, cudaFuncAttributeMaxDynamicSharedMemorySize,
                       LOGITS_SMEM);

  zero_state<<<64, 256>>>();
  build_rowlist<<<1, 256>>>(dec_len);
  zero_invalid_logits<<<dim3(32, 1024), 256>>>(dec_len, out);
  conv_W<<<NV, 256>>>(out_kernel);   // NV*256*4 == NH*NV exactly

  // Zx precompute: emb-gather GEMMs [1024 x 4096 x 256] with bias
  sgemm_db<<<dim3(32, 8), 256>>>(NB*NT, NG, NE, embedding, enc_kernel, enc_bias,
                                 zx_enc, enc_in, nullptr, nullptr);
  sgemm_db<<<dim3(32, 8), 256>>>(NB*NT, NG, NE, embedding, dec_kernel, dec_bias,
                                 zx_dec, dec_in, nullptr, nullptr);

  // ---- encoder ----
  for (int t = 0; t < NT; t++) {
    skinny_gemm<<<dim3(32, 16), 256>>>(hbuf, NH, enc_Wrec, NG, zpart, NG, NH);
    enc_step_gates<<<64, 256>>>(t, enc_len);
  }

  // keys = memory @ Wm  [1024 x 1024 x 1024]
  sgemm_db<<<dim3(8, 8), 256>>>(NB*NT, NH, NH, mem, Wm, nullptr, keys,
                                nullptr, nullptr, nullptr);

  // ---- decoder ----
  dec_init<<<128, 256>>>();
  for (int t = 0; t < NT; t++) {
    skinny_gemm<<<dim3(32, 16), 256>>>(attn_h, 2*NH, dec_Wrec, NG, zpart, NG, 2*NH);
    dec_step_gates<<<64, 256>>>(t);
    skinny_gemm<<<dim3(8, 16), 256>>>(h_ctx, 2*NH, Wq, NH, qpart, NH, NH);
    attn_scores<<<128, 256>>>(enc_len, v_att);
    softmax_ctx<<<64, 256>>>();
    skinny_gemm<<<dim3(8, 16), 256>>>(h_ctx, 2*NH, attn_kernel, NH, apart, NH, 2*NH);
    attn_out<<<64, 256>>>(t, dec_len);
  }

  // compact + split dec_out rows to bf16 hi/lo, then tensor-core logits GEMM
  conv_A<<<1024, 256>>>();
  logits_mma<<<dim3(500, 8), 256, LOGITS_SMEM>>>(ahi, alo, whi, wlo, out,
                                                 rowscat, mpad);
}

// round 11
// speedup vs baseline: 3.4558x; 1.1705x over previous
#include <cuda_runtime.h>
#include <cuda_bf16.h>
#include <stdint.h>
#include <math.h>
#include <string.h>

#define NB 16
#define NT 64
#define NV 32000
#define NE 256
#define NH 1024
#define NG 4096   // 4*H

// ---------------- device scratch (no allocs allowed) ----------------
__device__ float g_zx_enc[NB*NT*NG];
__device__ float g_zx_dec[NB*NT*NG];
__device__ float g_memory[NB*NT*NH];
__device__ float g_keys[NB*NT*NH];
__device__ float g_dec_out[NB*NT*NH];
__device__ float g_zpart[16*NB*NG];
__device__ float g_qpart[16*NB*NH];
__device__ float g_apart[16*NB*NH];
__device__ float g_h[NB*NH];
__device__ float g_c[NB*NH];
__device__ float g_attn_h[NB*2*NH];      // [attn | h] per batch (decoder recurrent input)
__device__ float g_h_ctx[NB*2*NH];       // [h2 | context] per batch
__device__ float g_scores[NB*NT];
__device__ int   g_rowidx[NB*NT];
__device__ int   g_rowscat[NB*NT];
__device__ int   g_mpad;
// bf16 hi/lo split operands
__device__ __nv_bfloat16 g_Whi[(size_t)NH*NV];
__device__ __nv_bfloat16 g_Wlo[(size_t)NH*NV];
__device__ __nv_bfloat16 g_Ahi[(size_t)NB*NT*NH];
__device__ __nv_bfloat16 g_Alo[(size_t)NB*NT*NH];
// recurrent weights hi/lo: [enc 4M | dec 8M | wq 1M | wa 2M] = 15M elems
#define RW_ENC 0
#define RW_DEC (4*1024*1024)
#define RW_WQ  (12*1024*1024)
#define RW_WA  (13*1024*1024)
__device__ __nv_bfloat16 g_RWhi[15*1024*1024];
__device__ __nv_bfloat16 g_RWlo[15*1024*1024];
// recurrent activations hi/lo
__device__ __nv_bfloat16 g_ye_hi[NB*NH],   g_ye_lo[NB*NH];     // encoder h
__device__ __nv_bfloat16 g_ya_hi[NB*2*NH], g_ya_lo[NB*2*NH];   // [attn | h]
__device__ __nv_bfloat16 g_yc_hi[NB*2*NH], g_yc_lo[NB*2*NH];   // [h2 | ctx]

__device__ __forceinline__ float sigm(float x){ return 1.f/(1.f + __expf(-x)); }
__device__ __forceinline__ float ftanh(float x){
  float a = fabsf(x);
  float e = __expf(-2.f * a);
  float t = (1.f - e) / (1.f + e);
  return copysignf(t, x);
}
__device__ __forceinline__ void bsplit(float v, __nv_bfloat16& h, __nv_bfloat16& l){
  h = __float2bfloat16_rn(v);
  l = __float2bfloat16_rn(v - __bfloat162float(h));
}

__device__ __forceinline__ unsigned smem_u32(const void* p){
  return (unsigned)__cvta_generic_to_shared(p);
}
__device__ __forceinline__ void cp16(unsigned dst, const void* src){
  asm volatile("cp.async.cg.shared.global [%0], [%1], 16;\n" :: "r"(dst), "l"(src));
}
__device__ __forceinline__ void cp4(unsigned dst, const void* src){
  asm volatile("cp.async.ca.shared.global [%0], [%1], 4;\n" :: "r"(dst), "l"(src));
}
__device__ __forceinline__ void cp_commit(){
  asm volatile("cp.async.commit_group;\n");
}
__device__ __forceinline__ void cp_wait0(){
  asm volatile("cp.async.wait_group 0;\n");
}

// ---------------- mma.sync helpers (R10-proven) ----------------
__device__ __forceinline__ void ldm4(unsigned* r, unsigned a){
  asm volatile("ldmatrix.sync.aligned.m8n8.x4.shared.b16 {%0,%1,%2,%3}, [%4];"
    : "=r"(r[0]), "=r"(r[1]), "=r"(r[2]), "=r"(r[3]) : "r"(a));
}
__device__ __forceinline__ void ldm4t(unsigned* r, unsigned a){
  asm volatile("ldmatrix.sync.aligned.m8n8.x4.trans.shared.b16 {%0,%1,%2,%3}, [%4];"
    : "=r"(r[0]), "=r"(r[1]), "=r"(r[2]), "=r"(r[3]) : "r"(a));
}
__device__ __forceinline__ void mma_bf16(float* c, const unsigned* a,
                                         unsigned b0, unsigned b1){
  asm volatile(
    "mma.sync.aligned.m16n8k16.row.col.f32.bf16.bf16.f32 "
    "{%0,%1,%2,%3}, {%4,%5,%6,%7}, {%8,%9}, {%0,%1,%2,%3};"
    : "+f"(c[0]), "+f"(c[1]), "+f"(c[2]), "+f"(c[3])
    : "r"(a[0]), "r"(a[1]), "r"(a[2]), "r"(a[3]), "r"(b0), "r"(b1));
}
__device__ __forceinline__ unsigned pkbf2(__nv_bfloat16 a, __nv_bfloat16 b){
  __nv_bfloat162 t;
  t.x = a;
  t.y = b;
  unsigned u;
  memcpy(&u, &t, 4);
  return u;
}

// =====================================================================
// Generic fp32 -> (hi, lo) bf16 split. grid = count/1024, block 256.
// =====================================================================
__global__ void conv_split(const float* __restrict__ src,
                           __nv_bfloat16* __restrict__ hi,
                           __nv_bfloat16* __restrict__ lo)
{
  size_t i = ((size_t)blockIdx.x * 256 + threadIdx.x) * 4;
  float4 v = *(const float4*)(src + i);
  __nv_bfloat16 h0, h1, h2, h3, l0, l1, l2, l3;
  bsplit(v.x, h0, l0);
  bsplit(v.y, h1, l1);
  bsplit(v.z, h2, l2);
  bsplit(v.w, h3, l3);
  *(uint2*)(hi + i) = make_uint2(pkbf2(h0, h1), pkbf2(h2, h3));
  *(uint2*)(lo + i) = make_uint2(pkbf2(l0, l1), pkbf2(l2, l3));
}

__global__ void conv_A()
{
  size_t i = ((size_t)blockIdx.x * 256 + threadIdx.x) * 4;
  int row = (int)(i >> 10);
  int k = (int)(i & 1023);
  int src = g_rowidx[row];
  float4 v = *(const float4*)(g_dec_out + (size_t)src * NH + k);
  __nv_bfloat16 h0, h1, h2, h3, l0, l1, l2, l3;
  bsplit(v.x, h0, l0);
  bsplit(v.y, h1, l1);
  bsplit(v.z, h2, l2);
  bsplit(v.w, h3, l3);
  *(uint2*)(g_Ahi + i) = make_uint2(pkbf2(h0, h1), pkbf2(h2, h3));
  *(uint2*)(g_Alo + i) = make_uint2(pkbf2(l0, l1), pkbf2(l2, l3));
}

// =====================================================================
// Skinny recurrent GEMM via mma.sync bf16 (hi/lo, fp32 accum), M=16.
// part[(ksplit*16 + b)*N + n] = sum_{k in chunk} y[b][k] * W[k][n]
// grid (N/128, KS), block 256 = 8 warps x 16 n-cols. Kblk = K/KS,
// multiple of 32. smem: y slab [16][Kblk] hi/lo + B double-buffer.
// Layout (bytes): yhi 0, ylo 8448, B 16896 + buf*17408 (+8704 lo).
// Dynamic smem = 51712.
// =====================================================================
__global__ __launch_bounds__(256, 2) void skinny_mma(
    const __nv_bfloat16* __restrict__ yhi, const __nv_bfloat16* __restrict__ ylo,
    int ystride,
    const __nv_bfloat16* __restrict__ Whi, const __nv_bfloat16* __restrict__ Wlo,
    float* __restrict__ part, int N, int K)
{
  extern __shared__ __align__(128) char sm[];
  const unsigned sb = smem_u32(sm);
  const int tid = threadIdx.x;
  const int lane = tid & 31;
  const int wid = tid >> 5;
  const int Kblk = K / gridDim.y;
  const int kbase = blockIdx.y * Kblk;
  const int nblk = blockIdx.x * 128;
  const int astride = Kblk*2 + 16;

  // stage y slab (hi/lo)
  for (int i = tid; i < 16*Kblk; i += 256) {
    int b = i / Kblk;
    int k = i - b*Kblk;
    *(__nv_bfloat16*)(sm + b*astride + k*2)        = yhi[b*ystride + kbase + k];
    *(__nv_bfloat16*)(sm + 8448 + b*astride + k*2) = ylo[b*ystride + kbase + k];
  }

  // prologue: B buf0 = W rows kbase..+31, cols nblk..+127
#pragma unroll
  for (int rep = 0; rep < 2; rep++) {
    int i = tid + rep*256;
    int kr = i >> 4;
    int q = i & 15;
    unsigned dst = sb + 16896 + kr*272 + q*16;
    cp16(dst,        Whi + (size_t)(kbase + kr) * N + nblk + q*8);
    cp16(dst + 8704, Wlo + (size_t)(kbase + kr) * N + nblk + q*8);
  }
  cp_commit();

  float acc[2][4];
#pragma unroll
  for (int j = 0; j < 2; j++)
#pragma unroll
    for (int e = 0; e < 4; e++) acc[j][e] = 0.f;

  const int KT = Kblk >> 5;
  for (int kt = 0; kt < KT; kt++) {
    cp_wait0();
    __syncthreads();
    if (kt + 1 < KT) {
      int kc = kbase + (kt+1)*32;
      int nb = (kt+1) & 1;
#pragma unroll
      for (int rep = 0; rep < 2; rep++) {
        int i = tid + rep*256;
        int kr = i >> 4;
        int q = i & 15;
        unsigned dst = sb + 16896 + nb*17408 + kr*272 + q*16;
        cp16(dst,        Whi + (size_t)(kc + kr) * N + nblk + q*8);
        cp16(dst + 8704, Wlo + (size_t)(kc + kr) * N + nblk + q*8);
      }
      cp_commit();
    }
    const unsigned bB = sb + 16896 + (unsigned)((kt & 1) * 17408);
#pragma unroll
    for (int ks = 0; ks < 2; ks++) {
      unsigned aH[4], aL[4], bH[4], bL[4];
      const int ar = lane & 15;
      const int ak = (lane >> 4) * 8;
      unsigned ad = sb + (unsigned)(ar*astride + (kt*32 + ks*16 + ak)*2);
      ldm4(aH, ad);
      ldm4(aL, ad + 8448);
      const int krow = ks*16 + ((lane >> 3) & 1)*8 + (lane & 7);
      const int nc = wid*16 + (lane >> 4)*8;
      unsigned bd = bB + (unsigned)(krow*272 + nc*2);
      ldm4t(bH, bd);
      ldm4t(bL, bd + 8704);
#pragma unroll
      for (int j = 0; j < 2; j++) {
        mma_bf16(acc[j], aH, bH[2*j], bH[2*j+1]);
        mma_bf16(acc[j], aH, bL[2*j], bL[2*j+1]);
        mma_bf16(acc[j], aL, bH[2*j], bH[2*j+1]);
      }
    }
  }

  // write partials: rows g, g+8 (batches); cols nblk + wid*16 + j*8 + (lane&3)*2
  const int g = lane >> 2;
  const int cn = (lane & 3) * 2;
#pragma unroll
  for (int j = 0; j < 2; j++) {
    int col = nblk + wid*16 + j*8 + cn;
    *(float2*)(part + (size_t)(blockIdx.y*16 + g) * N + col) =
        make_float2(acc[j][0], acc[j][1]);
    *(float2*)(part + (size_t)(blockIdx.y*16 + g + 8) * N + col) =
        make_float2(acc[j][2], acc[j][3]);
  }
}

// =====================================================================
// Logits GEMM via mma.sync (R10-proven)
// =====================================================================
__global__ __launch_bounds__(256, 2) void logits_mma(
    const __nv_bfloat16* __restrict__ Ahi, const __nv_bfloat16* __restrict__ Alo,
    const __nv_bfloat16* __restrict__ Whi, const __nv_bfloat16* __restrict__ Wlo,
    float* __restrict__ C, const int* __restrict__ rowC,
    const int* __restrict__ mlimit)
{
  extern __shared__ __align__(128) char sm[];
  const int mbase = blockIdx.y * 128;
  if (mbase >= *mlimit) return;
  const int n0 = blockIdx.x * 64;

  const unsigned sb = smem_u32(sm);
  const int tid = threadIdx.x;
  const int lane = tid & 31;
  const int wid = tid >> 5;
  const int wm = wid & 3;
  const int wn = wid >> 2;

  float acc[2][4][4];
#pragma unroll
  for (int mt = 0; mt < 2; mt++)
#pragma unroll
    for (int nt = 0; nt < 4; nt++)
#pragma unroll
      for (int e = 0; e < 4; e++) acc[mt][nt][e] = 0.f;

#pragma unroll
  for (int rep = 0; rep < 2; rep++) {
    int i = tid + rep * 256;
    int m = i >> 2;
    int q = i & 3;
    unsigned dst = sb + m*80 + q*16;
    cp16(dst,         Ahi + (size_t)(mbase + m) * NH + q*8);
    cp16(dst + 10240, Alo + (size_t)(mbase + m) * NH + q*8);
  }
  {
    int kr = tid >> 3;
    int q = tid & 7;
    unsigned dst = sb + 40960 + kr*144 + q*16;
    cp16(dst,        Whi + (size_t)kr * NV + n0 + q*8);
    cp16(dst + 4608, Wlo + (size_t)kr * NV + n0 + q*8);
  }
  cp_commit();

  for (int kt = 0; kt < 32; kt++) {
    cp_wait0();
    __syncthreads();
    if (kt + 1 < 32) {
      const int kc = (kt + 1) * 32;
      const int nb = (kt + 1) & 1;
#pragma unroll
      for (int rep = 0; rep < 2; rep++) {
        int i = tid + rep * 256;
        int m = i >> 2;
        int q = i & 3;
        unsigned dst = sb + nb*20480 + m*80 + q*16;
        cp16(dst,         Ahi + (size_t)(mbase + m) * NH + kc + q*8);
        cp16(dst + 10240, Alo + (size_t)(mbase + m) * NH + kc + q*8);
      }
      {
        int kr = tid >> 3;
        int q = tid & 7;
        unsigned dst = sb + 40960 + nb*9216 + kr*144 + q*16;
        cp16(dst,        Whi + (size_t)(kc + kr) * NV + n0 + q*8);
        cp16(dst + 4608, Wlo + (size_t)(kc + kr) * NV + n0 + q*8);
      }
      cp_commit();
    }

    const int buf = kt & 1;
    const unsigned aB = sb + buf*20480;
    const unsigned bB = sb + 40960 + buf*9216;

#pragma unroll
    for (int ks = 0; ks < 2; ks++) {
      unsigned aH[2][4], aL[2][4], bH[2][4], bL[2][4];
      const int ar = lane & 15;
      const int ak = (lane >> 4) * 8;
#pragma unroll
      for (int mt = 0; mt < 2; mt++) {
        unsigned ad = aB + (unsigned)((wm*32 + mt*16 + ar)*80 + (ks*16 + ak)*2);
        ldm4(aH[mt], ad);
        ldm4(aL[mt], ad + 10240);
      }
      const int krow = ks*16 + ((lane >> 3) & 1)*8 + (lane & 7);
#pragma unroll
      for (int p = 0; p < 2; p++) {
        int nc = wn*32 + p*16 + (lane >> 4)*8;
        unsigned bd = bB + (unsigned)(krow*144 + nc*2);
        ldm4t(bH[p], bd);
        ldm4t(bL[p], bd + 4608);
      }
#pragma unroll
      for (int mt = 0; mt < 2; mt++)
#pragma unroll
        for (int p = 0; p < 2; p++)
#pragma unroll
          for (int j = 0; j < 2; j++) {
            int nt = p*2 + j;
            mma_bf16(acc[mt][nt], aH[mt], bH[p][2*j], bH[p][2*j+1]);
            mma_bf16(acc[mt][nt], aH[mt], bL[p][2*j], bL[p][2*j+1]);
            mma_bf16(acc[mt][nt], aL[mt], bH[p][2*j], bH[p][2*j+1]);
          }
    }
  }

  const int g = lane >> 2;
  const int c0n = (lane & 3) * 2;
#pragma unroll
  for (int mt = 0; mt < 2; mt++) {
    int r0 = wm*32 + mt*16 + g;
    int sc0 = rowC[mbase + r0];
    int sc1 = rowC[mbase + r0 + 8];
#pragma unroll
    for (int nt = 0; nt < 4; nt++) {
      int col = n0 + wn*32 + nt*8 + c0n;
      if (sc0 >= 0)
        *(float2*)(C + (size_t)sc0 * NV + col) = make_float2(acc[mt][nt][0], acc[mt][nt][1]);
      if (sc1 >= 0)
        *(float2*)(C + (size_t)sc1 * NV + col) = make_float2(acc[mt][nt][2], acc[mt][nt][3]);
    }
  }
}

// =====================================================================
// cp.async double-buffered SGEMM (R7-proven): C = gatherA @ W (+bias).
// =====================================================================
__global__ __launch_bounds__(256, 2) void sgemm_db(
    int M, int N, int K,
    const float* __restrict__ A, const float* __restrict__ W,
    const float* __restrict__ bias, float* __restrict__ C,
    const int* __restrict__ rowA, const int* __restrict__ rowC,
    const int* __restrict__ mlimit)
{
  __shared__ float As[2][8][128];
  __shared__ float Bs[2][8][128];
  const int mbase = blockIdx.y * 128;
  if (mlimit && mbase >= *mlimit) return;
  const int nbase = blockIdx.x * 128;
  const int tid = threadIdx.x;
  const int tx = tid & 15;
  const int ty = tid >> 4;
  const int arow = tid >> 1;
  const int acol = (tid & 1) << 2;
  const int brow = tid >> 5;
  const int bcol = (tid & 31) << 2;
  int aIdx = mbase + arow;
  if (rowA) aIdx = rowA[aIdx];
  const float* Ap = A + (size_t)aIdx * K + acol;
  const float* Wp = W + (size_t)brow * N + nbase + bcol;

  unsigned sA[2][4];
  unsigned sB[2];
#pragma unroll
  for (int bf = 0; bf < 2; bf++) {
#pragma unroll
    for (int qq = 0; qq < 4; qq++) sA[bf][qq] = smem_u32(&As[bf][acol + qq][arow]);
    sB[bf] = smem_u32(&Bs[bf][brow][bcol]);
  }

  float acc[8][8];
#pragma unroll
  for (int i = 0; i < 8; i++)
#pragma unroll
    for (int j = 0; j < 8; j++) acc[i][j] = 0.f;

  const int KT = K >> 3;
#pragma unroll
  for (int qq = 0; qq < 4; qq++) cp4(sA[0][qq], Ap + qq);
  cp16(sB[0], Wp);
  cp_commit();

  for (int kt = 0; kt < KT; kt++) {
    cp_wait0();
    __syncthreads();
    if (kt + 1 < KT) {
      const float* Ap2 = Ap + (kt + 1) * 8;
      const float* Wp2 = Wp + (size_t)(kt + 1) * 8 * N;
      int nb = (kt + 1) & 1;
#pragma unroll
      for (int qq = 0; qq < 4; qq++) cp4(sA[nb][qq], Ap2 + qq);
      cp16(sB[nb], Wp2);
      cp_commit();
    }
    int cb = kt & 1;
#pragma unroll
    for (int kk = 0; kk < 8; kk++) {
      float ar[8];
      float br[8];
#pragma unroll
      for (int i = 0; i < 8; i++) ar[i] = As[cb][kk][ty*8 + i];
#pragma unroll
      for (int j = 0; j < 8; j++) br[j] = Bs[cb][kk][tx*8 + j];
#pragma unroll
      for (int i = 0; i < 8; i++)
#pragma unroll
        for (int j = 0; j < 8; j++) acc[i][j] += ar[i] * br[j];
    }
  }

  float bvals[8];
#pragma unroll
  for (int j = 0; j < 8; j++) bvals[j] = bias ? bias[nbase + tx*8 + j] : 0.f;
#pragma unroll
  for (int i = 0; i < 8; i++) {
    int crow = mbase + ty*8 + i;
    int cIdx = rowC ? rowC[crow] : crow;
    if (cIdx < 0) continue;
    float* cp = C + (size_t)cIdx * N + nbase + tx*8;
    float4 o0 = make_float4(acc[i][0]+bvals[0], acc[i][1]+bvals[1],
                            acc[i][2]+bvals[2], acc[i][3]+bvals[3]);
    float4 o1 = make_float4(acc[i][4]+bvals[4], acc[i][5]+bvals[5],
                            acc[i][6]+bvals[6], acc[i][7]+bvals[7]);
    *(float4*)(cp)     = o0;
    *(float4*)(cp + 4) = o1;
  }
}

// =====================================================================
// Small kernels
// =====================================================================
__global__ void zero_state()
{
  int idx = blockIdx.x * 256 + threadIdx.x;
  g_h[idx] = 0.f;
  g_c[idx] = 0.f;
  g_ye_hi[idx] = __float2bfloat16(0.f);
  g_ye_lo[idx] = __float2bfloat16(0.f);
}

__global__ void build_rowlist(const int* __restrict__ dec_len)
{
  __shared__ int off[17];
  if (threadIdx.x == 0) {
    int s = 0;
    off[0] = 0;
    for (int b = 0; b < NB; b++) {
      s += dec_len[b];
      off[b+1] = s;
    }
    g_mpad = (s + 127) & ~127;
  }
  __syncthreads();
  int nv = off[16];
  int mpad = (nv + 127) & ~127;
  for (int i = threadIdx.x; i < NB*NT; i += 256) {
    if (i < nv) {
      int b = 0;
      while (off[b+1] <= i) b++;
      int r = b*NT + (i - off[b]);
      g_rowidx[i] = r;
      g_rowscat[i] = r;
    } else if (i < mpad) {
      g_rowidx[i] = 0;
      g_rowscat[i] = -1;
    }
  }
}

__global__ void zero_invalid_logits(const int* __restrict__ dec_len, float* __restrict__ out)
{
  int row = blockIdx.y;
  int b = row >> 6;
  int t = row & 63;
  if (t < dec_len[b]) return;
  int c = (blockIdx.x * 256 + threadIdx.x) * 4;
  if (c < NV) {
    *(float4*)(out + (size_t)row * NV + c) = make_float4(0.f, 0.f, 0.f, 0.f);
  }
}

__global__ void enc_step_gates(int t, int ns, const int* __restrict__ enc_len)
{
  int idx = blockIdx.x * 256 + threadIdx.x;
  int b = idx >> 10;
  int j = idx & 1023;
  size_t zo = (size_t)(b*NT + t) * NG + j;
  float zi = g_zx_enc[zo];
  float zj = g_zx_enc[zo+1024];
  float zf = g_zx_enc[zo+2048];
  float zoo = g_zx_enc[zo+3072];
#pragma unroll 4
  for (int s = 0; s < ns; s++) {
    size_t po = (size_t)(s*16 + b) * NG + j;
    zi += g_zpart[po];
    zj += g_zpart[po+1024];
    zf += g_zpart[po+2048];
    zoo += g_zpart[po+3072];
  }
  float cn = g_c[idx] * sigm(zf + 1.f) + sigm(zi) * ftanh(zj);
  float hn = ftanh(cn) * sigm(zoo);
  bool valid = t < enc_len[b];
  if (valid) {
    g_h[idx] = hn;
    g_c[idx] = cn;
    bsplit(hn, g_ye_hi[idx], g_ye_lo[idx]);
  }
  g_memory[(size_t)(b*NT + t) * NH + j] = valid ? hn : 0.f;
}

__global__ void dec_init()
{
  int idx = blockIdx.x * 256 + threadIdx.x;
  int b = idx >> 11;
  int j = idx & 2047;
  float v = (j < 1024) ? 0.f : g_h[b*NH + (j - 1024)];
  g_attn_h[idx] = v;
  bsplit(v, g_ya_hi[idx], g_ya_lo[idx]);
}

__global__ void dec_step_gates(int t, int ns)
{
  int idx = blockIdx.x * 256 + threadIdx.x;
  int b = idx >> 10;
  int j = idx & 1023;
  size_t zo = (size_t)(b*NT + t) * NG + j;
  float zi = g_zx_dec[zo];
  float zj = g_zx_dec[zo+1024];
  float zf = g_zx_dec[zo+2048];
  float zoo = g_zx_dec[zo+3072];
#pragma unroll 4
  for (int s = 0; s < ns; s++) {
    size_t po = (size_t)(s*16 + b) * NG + j;
    zi += g_zpart[po];
    zj += g_zpart[po+1024];
    zf += g_zpart[po+2048];
    zoo += g_zpart[po+3072];
  }
  float cn = g_c[idx] * sigm(zf + 1.f) + sigm(zi) * ftanh(zj);
  float hn = ftanh(cn) * sigm(zoo);
  g_c[idx] = cn;
  g_attn_h[b*2*NH + NH + j] = hn;
  g_h_ctx[b*2*NH + j] = hn;
  __nv_bfloat16 hh, ll;
  bsplit(hn, hh, ll);
  g_ya_hi[b*2*NH + NH + j] = hh;
  g_ya_lo[b*2*NH + NH + j] = ll;
  g_yc_hi[b*2*NH + j] = hh;
  g_yc_lo[b*2*NH + j] = ll;
}

__global__ __launch_bounds__(256) void attn_scores(
    const int* __restrict__ enc_len, const float* __restrict__ v_att)
{
  __shared__ float sq[NH];
  __shared__ float sv[NH];
  int b = blockIdx.x >> 3;
  int tg = blockIdx.x & 7;
  int tid = threadIdx.x;
  for (int hh = tid; hh < NH; hh += 256) {
    float qv = 0.f;
#pragma unroll 4
    for (int s = 0; s < 16; s++) qv += g_qpart[(size_t)(s*16 + b) * NH + hh];
    sq[hh] = qv;
    sv[hh] = v_att[hh];
  }
  __syncthreads();
  int wid = tid >> 5;
  int lane = tid & 31;
  int tt = tg * 8 + wid;
  const float* krow = g_keys + (size_t)(b*NT + tt) * NH;
  float acc = 0.f;
  for (int h0 = lane; h0 < NH; h0 += 32)
    acc += ftanh(krow[h0] + sq[h0]) * sv[h0];
#pragma unroll
  for (int o = 16; o; o >>= 1) acc += __shfl_xor_sync(0xffffffffu, acc, o);
  if (lane == 0) g_scores[b*NT + tt] = (tt < enc_len[b]) ? acc : -1e9f;
}

__global__ __launch_bounds__(256) void softmax_ctx()
{
  __shared__ float sal[NT];
  int b = blockIdx.x >> 2;
  int hc = blockIdx.x & 3;
  int tid = threadIdx.x;
  if (tid < NT) sal[tid] = g_scores[b*NT + tid];
  __syncthreads();
  float mx = -3e38f;
#pragma unroll
  for (int t2 = 0; t2 < NT; t2++) mx = fmaxf(mx, sal[t2]);
  __syncthreads();
  if (tid < NT) sal[tid] = __expf(sal[tid] - mx);
  __syncthreads();
  float sum = 0.f;
#pragma unroll
  for (int t2 = 0; t2 < NT; t2++) sum += sal[t2];
  float inv = 1.f / sum;
  int h = hc * 256 + tid;
  const float* mb = g_memory + (size_t)b * NT * NH + h;
  float ctx = 0.f;
#pragma unroll 8
  for (int t2 = 0; t2 < NT; t2++) ctx += sal[t2] * mb[(size_t)t2 * NH];
  float v = ctx * inv;
  g_h_ctx[b*2*NH + NH + h] = v;
  bsplit(v, g_yc_hi[b*2*NH + NH + h], g_yc_lo[b*2*NH + NH + h]);
}

__global__ void attn_out(int t, const int* __restrict__ dec_len)
{
  int idx = blockIdx.x * 256 + threadIdx.x;
  int b = idx >> 10;
  int j = idx & 1023;
  float a = 0.f;
#pragma unroll 4
  for (int s = 0; s < 16; s++) a += g_apart[(size_t)(s*16 + b) * NH + j];
  g_attn_h[b*2*NH + j] = a;
  bsplit(a, g_ya_hi[b*2*NH + j], g_ya_lo[b*2*NH + j]);
  g_dec_out[(size_t)(b*NT + t) * NH + j] = (t >= dec_len[b]) ? 0.f : a;
}

// =====================================================================
// Host launch
// =====================================================================
extern "C" void kernel_launch(void* const* d_in, const int* in_sizes, int n_in,
                              void* d_out, int out_size)
{
  const int*   enc_in      = (const int*)d_in[0];
  const int*   dec_in      = (const int*)d_in[1];
  const int*   enc_len     = (const int*)d_in[2];
  const int*   dec_len     = (const int*)d_in[3];
  const float* embedding   = (const float*)d_in[4];
  const float* enc_kernel  = (const float*)d_in[5];
  const float* enc_bias    = (const float*)d_in[6];
  const float* dec_kernel  = (const float*)d_in[7];
  const float* dec_bias    = (const float*)d_in[8];
  const float* Wm          = (const float*)d_in[9];
  const float* Wq          = (const float*)d_in[10];
  const float* v_att       = (const float*)d_in[11];
  const float* attn_kernel = (const float*)d_in[12];
  const float* out_kernel  = (const float*)d_in[13];
  float* out = (float*)d_out;
  (void)in_sizes;
  (void)n_in;
  (void)out_size;

  float *zx_enc, *zx_dec, *mem, *keys, *dec_o, *zpart, *qpart, *apart;
  int *rowscat, *mpad;
  __nv_bfloat16 *whi, *wlo, *ahi, *alo, *rwhi, *rwlo;
  __nv_bfloat16 *yehi, *yelo, *yahi, *yalo, *ychi, *yclo;
  cudaGetSymbolAddress((void**)&zx_enc, g_zx_enc);
  cudaGetSymbolAddress((void**)&zx_dec, g_zx_dec);
  cudaGetSymbolAddress((void**)&mem,    g_memory);
  cudaGetSymbolAddress((void**)&keys,   g_keys);
  cudaGetSymbolAddress((void**)&dec_o,  g_dec_out);
  cudaGetSymbolAddress((void**)&zpart,  g_zpart);
  cudaGetSymbolAddress((void**)&qpart,  g_qpart);
  cudaGetSymbolAddress((void**)&apart,  g_apart);
  cudaGetSymbolAddress((void**)&rowscat, g_rowscat);
  cudaGetSymbolAddress((void**)&mpad,   g_mpad);
  cudaGetSymbolAddress((void**)&whi,    g_Whi);
  cudaGetSymbolAddress((void**)&wlo,    g_Wlo);
  cudaGetSymbolAddress((void**)&ahi,    g_Ahi);
  cudaGetSymbolAddress((void**)&alo,    g_Alo);
  cudaGetSymbolAddress((void**)&rwhi,   g_RWhi);
  cudaGetSymbolAddress((void**)&rwlo,   g_RWlo);
  cudaGetSymbolAddress((void**)&yehi,   g_ye_hi);
  cudaGetSymbolAddress((void**)&yelo,   g_ye_lo);
  cudaGetSymbolAddress((void**)&yahi,   g_ya_hi);
  cudaGetSymbolAddress((void**)&yalo,   g_ya_lo);
  cudaGetSymbolAddress((void**)&ychi,   g_yc_hi);
  cudaGetSymbolAddress((void**)&yclo,   g_yc_lo);

  const int LOGITS_SMEM = 2*2*10240 + 2*2*4608;  // 59392
  const int SKINNY_SMEM = 16896 + 2*2*8704;      // 51712
  cudaFuncSetAttribute(logits_mma, cudaFuncAttributeMaxDynamicSharedMemorySize,
                       LOGITS_SMEM);
  cudaFuncSetAttribute(skinny_mma, cudaFuncAttributeMaxDynamicSharedMemorySize,
                       SKINNY_SMEM);

  zero_state<<<64, 256>>>();
  build_rowlist<<<1, 256>>>(dec_len);
  zero_invalid_logits<<<dim3(32, 1024), 256>>>(dec_len, out);

  // fp32 -> bf16 hi/lo weight splits (once)
  conv_split<<<NV, 256>>>(out_kernel, whi, wlo);                        // 32.768M
  conv_split<<<4096, 256>>>(enc_kernel + (size_t)NE*NG, rwhi + RW_ENC, rwlo + RW_ENC);
  conv_split<<<8192, 256>>>(dec_kernel + (size_t)NE*NG, rwhi + RW_DEC, rwlo + RW_DEC);
  conv_split<<<1024, 256>>>(Wq,          rwhi + RW_WQ,  rwlo + RW_WQ);
  conv_split<<<2048, 256>>>(attn_kernel, rwhi + RW_WA,  rwlo + RW_WA);

  // Zx precompute: emb-gather GEMMs [1024 x 4096 x 256] with bias
  sgemm_db<<<dim3(32, 8), 256>>>(NB*NT, NG, NE, embedding, enc_kernel, enc_bias,
                                 zx_enc, enc_in, nullptr, nullptr);
  sgemm_db<<<dim3(32, 8), 256>>>(NB*NT, NG, NE, embedding, dec_kernel, dec_bias,
                                 zx_dec, dec_in, nullptr, nullptr);

  // ---- encoder ----  (z = h @ Wrec: N=4096, K=1024, KS=8)
  for (int t = 0; t < NT; t++) {
    skinny_mma<<<dim3(32, 8), 256, SKINNY_SMEM>>>(yehi, yelo, NH,
                                                  rwhi + RW_ENC, rwlo + RW_ENC,
                                                  zpart, NG, NH);
    enc_step_gates<<<64, 256>>>(t, 8, enc_len);
  }

  // keys = memory @ Wm  [1024 x 1024 x 1024]
  sgemm_db<<<dim3(8, 8), 256>>>(NB*NT, NH, NH, mem, Wm, nullptr, keys,
                                nullptr, nullptr, nullptr);

  // ---- decoder ----
  dec_init<<<128, 256>>>();
  for (int t = 0; t < NT; t++) {
    // z = zx + [attn|h] @ Wrec: N=4096, K=2048, KS=8
    skinny_mma<<<dim3(32, 8), 256, SKINNY_SMEM>>>(yahi, yalo, 2*NH,
                                                  rwhi + RW_DEC, rwlo + RW_DEC,
                                                  zpart, NG, 2*NH);
    dec_step_gates<<<64, 256>>>(t, 8);
    // query = h2 @ Wq: N=1024, K=1024, KS=16
    skinny_mma<<<dim3(8, 16), 256, SKINNY_SMEM>>>(ychi, yclo, 2*NH,
                                                  rwhi + RW_WQ, rwlo + RW_WQ,
                                                  qpart, NH, NH);
    attn_scores<<<128, 256>>>(enc_len, v_att);
    softmax_ctx<<<64, 256>>>();
    // attn2 = [h2|ctx] @ attn_kernel: N=1024, K=2048, KS=16
    skinny_mma<<<dim3(8, 16), 256, SKINNY_SMEM>>>(ychi, yclo, 2*NH,
                                                  rwhi + RW_WA, rwlo + RW_WA,
                                                  apart, NH, 2*NH);
    attn_out<<<64, 256>>>(t, dec_len);
  }

  // compact + split dec_out rows, then tensor-core logits GEMM
  conv_A<<<1024, 256>>>();
  logits_mma<<<dim3(500, 8), 256, LOGITS_SMEM>>>(ahi, alo, whi, wlo, out,
                                                 rowscat, mpad);
}

// round 13
// speedup vs baseline: 3.5463x; 1.0262x over previous
#include <cuda_runtime.h>
#include <cuda_bf16.h>
#include <stdint.h>
#include <math.h>
#include <string.h>

#define NB 16
#define NT 64
#define NV 32000
#define NE 256
#define NH 1024
#define NG 4096   // 4*H

// ---------------- device scratch (no allocs allowed) ----------------
__device__ float g_zx_enc[NB*NT*NG];
__device__ float g_zx_dec[NB*NT*NG];
__device__ float g_memory[NB*NT*NH];
__device__ float g_keys[NB*NT*NH];
__device__ float g_premem[NB*NT*NH];     // memory @ Wa2 (ctx half of attn_kernel)
__device__ float g_dec_out[NB*NT*NH];
__device__ float g_zpart[16*NB*NG];
__device__ float g_qapart[16*NB*2*NH];   // [q | h2@Wa1] K-split partials
__device__ float g_h[NB*NH];
__device__ float g_c[NB*NH];
__device__ float g_attn_h[NB*2*NH];      // [attn | h] per batch (decoder recurrent input)
__device__ float g_h_ctx[NB*2*NH];       // [h2 | -] per batch
__device__ float g_scores[NB*NT];
__device__ int   g_rowidx[NB*NT];
__device__ int   g_rowscat[NB*NT];
__device__ int   g_mpad;
// bf16 hi/lo split operands
__device__ __nv_bfloat16 g_Whi[(size_t)NH*NV];
__device__ __nv_bfloat16 g_Wlo[(size_t)NH*NV];
__device__ __nv_bfloat16 g_Ahi[(size_t)NB*NT*NH];
__device__ __nv_bfloat16 g_Alo[(size_t)NB*NT*NH];
// recurrent weights hi/lo: [enc 4M | dec 8M | qa 2M] = 14M elems
#define RW_ENC 0
#define RW_DEC (4*1024*1024)
#define RW_QA  (12*1024*1024)
__device__ __nv_bfloat16 g_RWhi[14*1024*1024];
__device__ __nv_bfloat16 g_RWlo[14*1024*1024];
// recurrent activations hi/lo
__device__ __nv_bfloat16 g_ye_hi[NB*NH],   g_ye_lo[NB*NH];     // encoder h
__device__ __nv_bfloat16 g_ya_hi[NB*2*NH], g_ya_lo[NB*2*NH];   // [attn | h]
__device__ __nv_bfloat16 g_yc_hi[NB*2*NH], g_yc_lo[NB*2*NH];   // [h2 | -]

__device__ __forceinline__ float sigm(float x){ return 1.f/(1.f + __expf(-x)); }
__device__ __forceinline__ float ftanh(float x){
  float a = fabsf(x);
  float e = __expf(-2.f * a);
  float t = (1.f - e) / (1.f + e);
  return copysignf(t, x);
}
__device__ __forceinline__ void bsplit(float v, __nv_bfloat16& h, __nv_bfloat16& l){
  h = __float2bfloat16_rn(v);
  l = __float2bfloat16_rn(v - __bfloat162float(h));
}

__device__ __forceinline__ unsigned smem_u32(const void* p){
  return (unsigned)__cvta_generic_to_shared(p);
}
__device__ __forceinline__ void cp16(unsigned dst, const void* src){
  asm volatile("cp.async.cg.shared.global [%0], [%1], 16;\n" :: "r"(dst), "l"(src));
}
__device__ __forceinline__ void cp4(unsigned dst, const void* src){
  asm volatile("cp.async.ca.shared.global [%0], [%1], 4;\n" :: "r"(dst), "l"(src));
}
__device__ __forceinline__ void cp_commit(){
  asm volatile("cp.async.commit_group;\n");
}
__device__ __forceinline__ void cp_wait0(){
  asm volatile("cp.async.wait_group 0;\n");
}

// ---------------- mma.sync helpers (R10/R11-proven) ----------------
__device__ __forceinline__ void ldm4(unsigned* r, unsigned a){
  asm volatile("ldmatrix.sync.aligned.m8n8.x4.shared.b16 {%0,%1,%2,%3}, [%4];"
    : "=r"(r[0]), "=r"(r[1]), "=r"(r[2]), "=r"(r[3]) : "r"(a));
}
__device__ __forceinline__ void ldm4t(unsigned* r, unsigned a){
  asm volatile("ldmatrix.sync.aligned.m8n8.x4.trans.shared.b16 {%0,%1,%2,%3}, [%4];"
    : "=r"(r[0]), "=r"(r[1]), "=r"(r[2]), "=r"(r[3]) : "r"(a));
}
__device__ __forceinline__ void mma_bf16(float* c, const unsigned* a,
                                         unsigned b0, unsigned b1){
  asm volatile(
    "mma.sync.aligned.m16n8k16.row.col.f32.bf16.bf16.f32 "
    "{%0,%1,%2,%3}, {%4,%5,%6,%7}, {%8,%9}, {%0,%1,%2,%3};"
    : "+f"(c[0]), "+f"(c[1]), "+f"(c[2]), "+f"(c[3])
    : "r"(a[0]), "r"(a[1]), "r"(a[2]), "r"(a[3]), "r"(b0), "r"(b1));
}
__device__ __forceinline__ unsigned pkbf2(__nv_bfloat16 a, __nv_bfloat16 b){
  __nv_bfloat162 t;
  t.x = a;
  t.y = b;
  unsigned u;
  memcpy(&u, &t, 4);
  return u;
}

// =====================================================================
// fp32 -> (hi, lo) bf16 splits
// =====================================================================
__global__ void conv_split(const float* __restrict__ src,
                           __nv_bfloat16* __restrict__ hi,
                           __nv_bfloat16* __restrict__ lo)
{
  size_t i = ((size_t)blockIdx.x * 256 + threadIdx.x) * 4;
  float4 v = *(const float4*)(src + i);
  __nv_bfloat16 h0, h1, h2, h3, l0, l1, l2, l3;
  bsplit(v.x, h0, l0);
  bsplit(v.y, h1, l1);
  bsplit(v.z, h2, l2);
  bsplit(v.w, h3, l3);
  *(uint2*)(hi + i) = make_uint2(pkbf2(h0, h1), pkbf2(h2, h3));
  *(uint2*)(lo + i) = make_uint2(pkbf2(l0, l1), pkbf2(l2, l3));
}

// Build combined [Wq | Wa1] weight block: QA[k][0..1023]=Wq[k], [1024..2047]=Wa1[k].
__global__ void conv_qa(const float* __restrict__ Wq, const float* __restrict__ Wa)
{
  size_t i = ((size_t)blockIdx.x * 256 + threadIdx.x) * 4;   // grid 2048 -> 2M elems
  int k = (int)(i >> 11);
  int col = (int)(i & 2047);
  const float* src = (col < 1024) ? (Wq + (size_t)k * NH + col)
                                  : (Wa + (size_t)k * NH + (col - 1024));
  float4 v = *(const float4*)src;
  __nv_bfloat16 h0, h1, h2, h3, l0, l1, l2, l3;
  bsplit(v.x, h0, l0);
  bsplit(v.y, h1, l1);
  bsplit(v.z, h2, l2);
  bsplit(v.w, h3, l3);
  *(uint2*)(g_RWhi + RW_QA + i) = make_uint2(pkbf2(h0, h1), pkbf2(h2, h3));
  *(uint2*)(g_RWlo + RW_QA + i) = make_uint2(pkbf2(l0, l1), pkbf2(l2, l3));
}

__global__ void conv_A()
{
  size_t i = ((size_t)blockIdx.x * 256 + threadIdx.x) * 4;
  int row = (int)(i >> 10);
  int k = (int)(i & 1023);
  int src = g_rowidx[row];
  float4 v = *(const float4*)(g_dec_out + (size_t)src * NH + k);
  __nv_bfloat16 h0, h1, h2, h3, l0, l1, l2, l3;
  bsplit(v.x, h0, l0);
  bsplit(v.y, h1, l1);
  bsplit(v.z, h2, l2);
  bsplit(v.w, h3, l3);
  *(uint2*)(g_Ahi + i) = make_uint2(pkbf2(h0, h1), pkbf2(h2, h3));
  *(uint2*)(g_Alo + i) = make_uint2(pkbf2(l0, l1), pkbf2(l2, l3));
}

// =====================================================================
// Skinny recurrent GEMM via mma.sync (R11-proven), M=16.
// =====================================================================
__global__ __launch_bounds__(256, 2) void skinny_mma(
    const __nv_bfloat16* __restrict__ yhi, const __nv_bfloat16* __restrict__ ylo,
    int ystride,
    const __nv_bfloat16* __restrict__ Whi, const __nv_bfloat16* __restrict__ Wlo,
    float* __restrict__ part, int N, int K)
{
  extern __shared__ __align__(128) char sm[];
  const unsigned sb = smem_u32(sm);
  const int tid = threadIdx.x;
  const int lane = tid & 31;
  const int wid = tid >> 5;
  const int Kblk = K / gridDim.y;
  const int kbase = blockIdx.y * Kblk;
  const int nblk = blockIdx.x * 128;
  const int astride = Kblk*2 + 16;

  for (int i = tid; i < 16*Kblk; i += 256) {
    int b = i / Kblk;
    int k = i - b*Kblk;
    *(__nv_bfloat16*)(sm + b*astride + k*2)        = yhi[b*ystride + kbase + k];
    *(__nv_bfloat16*)(sm + 8448 + b*astride + k*2) = ylo[b*ystride + kbase + k];
  }

#pragma unroll
  for (int rep = 0; rep < 2; rep++) {
    int i = tid + rep*256;
    int kr = i >> 4;
    int q = i & 15;
    unsigned dst = sb + 16896 + kr*272 + q*16;
    cp16(dst,        Whi + (size_t)(kbase + kr) * N + nblk + q*8);
    cp16(dst + 8704, Wlo + (size_t)(kbase + kr) * N + nblk + q*8);
  }
  cp_commit();

  float acc[2][4];
#pragma unroll
  for (int j = 0; j < 2; j++)
#pragma unroll
    for (int e = 0; e < 4; e++) acc[j][e] = 0.f;

  const int KT = Kblk >> 5;
  for (int kt = 0; kt < KT; kt++) {
    cp_wait0();
    __syncthreads();
    if (kt + 1 < KT) {
      int kc = kbase + (kt+1)*32;
      int nb = (kt+1) & 1;
#pragma unroll
      for (int rep = 0; rep < 2; rep++) {
        int i = tid + rep*256;
        int kr = i >> 4;
        int q = i & 15;
        unsigned dst = sb + 16896 + nb*17408 + kr*272 + q*16;
        cp16(dst,        Whi + (size_t)(kc + kr) * N + nblk + q*8);
        cp16(dst + 8704, Wlo + (size_t)(kc + kr) * N + nblk + q*8);
      }
      cp_commit();
    }
    const unsigned bB = sb + 16896 + (unsigned)((kt & 1) * 17408);
#pragma unroll
    for (int ks = 0; ks < 2; ks++) {
      unsigned aH[4], aL[4], bH[4], bL[4];
      const int ar = lane & 15;
      const int ak = (lane >> 4) * 8;
      unsigned ad = sb + (unsigned)(ar*astride + (kt*32 + ks*16 + ak)*2);
      ldm4(aH, ad);
      ldm4(aL, ad + 8448);
      const int krow = ks*16 + ((lane >> 3) & 1)*8 + (lane & 7);
      const int nc = wid*16 + (lane >> 4)*8;
      unsigned bd = bB + (unsigned)(krow*272 + nc*2);
      ldm4t(bH, bd);
      ldm4t(bL, bd + 8704);
#pragma unroll
      for (int j = 0; j < 2; j++) {
        mma_bf16(acc[j], aH, bH[2*j], bH[2*j+1]);
        mma_bf16(acc[j], aH, bL[2*j], bL[2*j+1]);
        mma_bf16(acc[j], aL, bH[2*j], bH[2*j+1]);
      }
    }
  }

  const int g = lane >> 2;
  const int cn = (lane & 3) * 2;
#pragma unroll
  for (int j = 0; j < 2; j++) {
    int col = nblk + wid*16 + j*8 + cn;
    *(float2*)(part + (size_t)(blockIdx.y*16 + g) * N + col) =
        make_float2(acc[j][0], acc[j][1]);
    *(float2*)(part + (size_t)(blockIdx.y*16 + g + 8) * N + col) =
        make_float2(acc[j][2], acc[j][3]);
  }
}

// =====================================================================
// Logits GEMM via mma.sync (R10-proven)
// =====================================================================
__global__ __launch_bounds__(256, 2) void logits_mma(
    const __nv_bfloat16* __restrict__ Ahi, const __nv_bfloat16* __restrict__ Alo,
    const __nv_bfloat16* __restrict__ Whi, const __nv_bfloat16* __restrict__ Wlo,
    float* __restrict__ C, const int* __restrict__ rowC,
    const int* __restrict__ mlimit)
{
  extern __shared__ __align__(128) char sm[];
  const int mbase = blockIdx.y * 128;
  if (mbase >= *mlimit) return;
  const int n0 = blockIdx.x * 64;

  const unsigned sb = smem_u32(sm);
  const int tid = threadIdx.x;
  const int lane = tid & 31;
  const int wid = tid >> 5;
  const int wm = wid & 3;
  const int wn = wid >> 2;

  float acc[2][4][4];
#pragma unroll
  for (int mt = 0; mt < 2; mt++)
#pragma unroll
    for (int nt = 0; nt < 4; nt++)
#pragma unroll
      for (int e = 0; e < 4; e++) acc[mt][nt][e] = 0.f;

#pragma unroll
  for (int rep = 0; rep < 2; rep++) {
    int i = tid + rep * 256;
    int m = i >> 2;
    int q = i & 3;
    unsigned dst = sb + m*80 + q*16;
    cp16(dst,         Ahi + (size_t)(mbase + m) * NH + q*8);
    cp16(dst + 10240, Alo + (size_t)(mbase + m) * NH + q*8);
  }
  {
    int kr = tid >> 3;
    int q = tid & 7;
    unsigned dst = sb + 40960 + kr*144 + q*16;
    cp16(dst,        Whi + (size_t)kr * NV + n0 + q*8);
    cp16(dst + 4608, Wlo + (size_t)kr * NV + n0 + q*8);
  }
  cp_commit();

  for (int kt = 0; kt < 32; kt++) {
    cp_wait0();
    __syncthreads();
    if (kt + 1 < 32) {
      const int kc = (kt + 1) * 32;
      const int nb = (kt + 1) & 1;
#pragma unroll
      for (int rep = 0; rep < 2; rep++) {
        int i = tid + rep * 256;
        int m = i >> 2;
        int q = i & 3;
        unsigned dst = sb + nb*20480 + m*80 + q*16;
        cp16(dst,         Ahi + (size_t)(mbase + m) * NH + kc + q*8);
        cp16(dst + 10240, Alo + (size_t)(mbase + m) * NH + kc + q*8);
      }
      {
        int kr = tid >> 3;
        int q = tid & 7;
        unsigned dst = sb + 40960 + nb*9216 + kr*144 + q*16;
        cp16(dst,        Whi + (size_t)(kc + kr) * NV + n0 + q*8);
        cp16(dst + 4608, Wlo + (size_t)(kc + kr) * NV + n0 + q*8);
      }
      cp_commit();
    }

    const int buf = kt & 1;
    const unsigned aB = sb + buf*20480;
    const unsigned bB = sb + 40960 + buf*9216;

#pragma unroll
    for (int ks = 0; ks < 2; ks++) {
      unsigned aH[2][4], aL[2][4], bH[2][4], bL[2][4];
      const int ar = lane & 15;
      const int ak = (lane >> 4) * 8;
#pragma unroll
      for (int mt = 0; mt < 2; mt++) {
        unsigned ad = aB + (unsigned)((wm*32 + mt*16 + ar)*80 + (ks*16 + ak)*2);
        ldm4(aH[mt], ad);
        ldm4(aL[mt], ad + 10240);
      }
      const int krow = ks*16 + ((lane >> 3) & 1)*8 + (lane & 7);
#pragma unroll
      for (int p = 0; p < 2; p++) {
        int nc = wn*32 + p*16 + (lane >> 4)*8;
        unsigned bd = bB + (unsigned)(krow*144 + nc*2);
        ldm4t(bH[p], bd);
        ldm4t(bL[p], bd + 4608);
      }
#pragma unroll
      for (int mt = 0; mt < 2; mt++)
#pragma unroll
        for (int p = 0; p < 2; p++)
#pragma unroll
          for (int j = 0; j < 2; j++) {
            int nt = p*2 + j;
            mma_bf16(acc[mt][nt], aH[mt], bH[p][2*j], bH[p][2*j+1]);
            mma_bf16(acc[mt][nt], aH[mt], bL[p][2*j], bL[p][2*j+1]);
            mma_bf16(acc[mt][nt], aL[mt], bH[p][2*j], bH[p][2*j+1]);
          }
    }
  }

  const int g = lane >> 2;
  const int c0n = (lane & 3) * 2;
#pragma unroll
  for (int mt = 0; mt < 2; mt++) {
    int r0 = wm*32 + mt*16 + g;
    int sc0 = rowC[mbase + r0];
    int sc1 = rowC[mbase + r0 + 8];
#pragma unroll
    for (int nt = 0; nt < 4; nt++) {
      int col = n0 + wn*32 + nt*8 + c0n;
      if (sc0 >= 0)
        *(float2*)(C + (size_t)sc0 * NV + col) = make_float2(acc[mt][nt][0], acc[mt][nt][1]);
      if (sc1 >= 0)
        *(float2*)(C + (size_t)sc1 * NV + col) = make_float2(acc[mt][nt][2], acc[mt][nt][3]);
    }
  }
}

// =====================================================================
// cp.async double-buffered SGEMM (R7-proven)
// =====================================================================
__global__ __launch_bounds__(256, 2) void sgemm_db(
    int M, int N, int K,
    const float* __restrict__ A, const float* __restrict__ W,
    const float* __restrict__ bias, float* __restrict__ C,
    const int* __restrict__ rowA, const int* __restrict__ rowC,
    const int* __restrict__ mlimit)
{
  __shared__ float As[2][8][128];
  __shared__ float Bs[2][8][128];
  const int mbase = blockIdx.y * 128;
  if (mlimit && mbase >= *mlimit) return;
  const int nbase = blockIdx.x * 128;
  const int tid = threadIdx.x;
  const int tx = tid & 15;
  const int ty = tid >> 4;
  const int arow = tid >> 1;
  const int acol = (tid & 1) << 2;
  const int brow = tid >> 5;
  const int bcol = (tid & 31) << 2;
  int aIdx = mbase + arow;
  if (rowA) aIdx = rowA[aIdx];
  const float* Ap = A + (size_t)aIdx * K + acol;
  const float* Wp = W + (size_t)brow * N + nbase + bcol;

  unsigned sA[2][4];
  unsigned sB[2];
#pragma unroll
  for (int bf = 0; bf < 2; bf++) {
#pragma unroll
    for (int qq = 0; qq < 4; qq++) sA[bf][qq] = smem_u32(&As[bf][acol + qq][arow]);
    sB[bf] = smem_u32(&Bs[bf][brow][bcol]);
  }

  float acc[8][8];
#pragma unroll
  for (int i = 0; i < 8; i++)
#pragma unroll
    for (int j = 0; j < 8; j++) acc[i][j] = 0.f;

  const int KT = K >> 3;
#pragma unroll
  for (int qq = 0; qq < 4; qq++) cp4(sA[0][qq], Ap + qq);
  cp16(sB[0], Wp);
  cp_commit();

  for (int kt = 0; kt < KT; kt++) {
    cp_wait0();
    __syncthreads();
    if (kt + 1 < KT) {
      const float* Ap2 = Ap + (kt + 1) * 8;
      const float* Wp2 = Wp + (size_t)(kt + 1) * 8 * N;
      int nb = (kt + 1) & 1;
#pragma unroll
      for (int qq = 0; qq < 4; qq++) cp4(sA[nb][qq], Ap2 + qq);
      cp16(sB[nb], Wp2);
      cp_commit();
    }
    int cb = kt & 1;
#pragma unroll
    for (int kk = 0; kk < 8; kk++) {
      float ar[8];
      float br[8];
#pragma unroll
      for (int i = 0; i < 8; i++) ar[i] = As[cb][kk][ty*8 + i];
#pragma unroll
      for (int j = 0; j < 8; j++) br[j] = Bs[cb][kk][tx*8 + j];
#pragma unroll
      for (int i = 0; i < 8; i++)
#pragma unroll
        for (int j = 0; j < 8; j++) acc[i][j] += ar[i] * br[j];
    }
  }

  float bvals[8];
#pragma unroll
  for (int j = 0; j < 8; j++) bvals[j] = bias ? bias[nbase + tx*8 + j] : 0.f;
#pragma unroll
  for (int i = 0; i < 8; i++) {
    int crow = mbase + ty*8 + i;
    int cIdx = rowC ? rowC[crow] : crow;
    if (cIdx < 0) continue;
    float* cp = C + (size_t)cIdx * N + nbase + tx*8;
    float4 o0 = make_float4(acc[i][0]+bvals[0], acc[i][1]+bvals[1],
                            acc[i][2]+bvals[2], acc[i][3]+bvals[3]);
    float4 o1 = make_float4(acc[i][4]+bvals[4], acc[i][5]+bvals[5],
                            acc[i][6]+bvals[6], acc[i][7]+bvals[7]);
    *(float4*)(cp)     = o0;
    *(float4*)(cp + 4) = o1;
  }
}

// =====================================================================
// Small kernels
// =====================================================================
__global__ void zero_state()
{
  int idx = blockIdx.x * 256 + threadIdx.x;
  g_h[idx] = 0.f;
  g_c[idx] = 0.f;
  g_ye_hi[idx] = __float2bfloat16(0.f);
  g_ye_lo[idx] = __float2bfloat16(0.f);
}

__global__ void build_rowlist(const int* __restrict__ dec_len)
{
  __shared__ int off[17];
  if (threadIdx.x == 0) {
    int s = 0;
    off[0] = 0;
    for (int b = 0; b < NB; b++) {
      s += dec_len[b];
      off[b+1] = s;
    }
    g_mpad = (s + 127) & ~127;
  }
  __syncthreads();
  int nv = off[16];
  int mpad = (nv + 127) & ~127;
  for (int i = threadIdx.x; i < NB*NT; i += 256) {
    if (i < nv) {
      int b = 0;
      while (off[b+1] <= i) b++;
      int r = b*NT + (i - off[b]);
      g_rowidx[i] = r;
      g_rowscat[i] = r;
    } else if (i < mpad) {
      g_rowidx[i] = 0;
      g_rowscat[i] = -1;
    }
  }
}

__global__ void zero_invalid_logits(const int* __restrict__ dec_len, float* __restrict__ out)
{
  int row = blockIdx.y;
  int b = row >> 6;
  int t = row & 63;
  if (t < dec_len[b]) return;
  int c = (blockIdx.x * 256 + threadIdx.x) * 4;
  if (c < NV) {
    *(float4*)(out + (size_t)row * NV + c) = make_float4(0.f, 0.f, 0.f, 0.f);
  }
}

__global__ void enc_step_gates(int t, int ns, const int* __restrict__ enc_len)
{
  int idx = blockIdx.x * 256 + threadIdx.x;
  int b = idx >> 10;
  int j = idx & 1023;
  size_t zo = (size_t)(b*NT + t) * NG + j;
  float zi = g_zx_enc[zo];
  float zj = g_zx_enc[zo+1024];
  float zf = g_zx_enc[zo+2048];
  float zoo = g_zx_enc[zo+3072];
#pragma unroll 4
  for (int s = 0; s < ns; s++) {
    size_t po = (size_t)(s*16 + b) * NG + j;
    zi += g_zpart[po];
    zj += g_zpart[po+1024];
    zf += g_zpart[po+2048];
    zoo += g_zpart[po+3072];
  }
  float cn = g_c[idx] * sigm(zf + 1.f) + sigm(zi) * ftanh(zj);
  float hn = ftanh(cn) * sigm(zoo);
  bool valid = t < enc_len[b];
  if (valid) {
    g_h[idx] = hn;
    g_c[idx] = cn;
    bsplit(hn, g_ye_hi[idx], g_ye_lo[idx]);
  }
  g_memory[(size_t)(b*NT + t) * NH + j] = valid ? hn : 0.f;
}

__global__ void dec_init()
{
  int idx = blockIdx.x * 256 + threadIdx.x;
  int b = idx >> 11;
  int j = idx & 2047;
  float v = (j < 1024) ? 0.f : g_h[b*NH + (j - 1024)];
  g_attn_h[idx] = v;
  bsplit(v, g_ya_hi[idx], g_ya_lo[idx]);
}

__global__ void dec_step_gates(int t, int ns)
{
  int idx = blockIdx.x * 256 + threadIdx.x;
  int b = idx >> 10;
  int j = idx & 1023;
  size_t zo = (size_t)(b*NT + t) * NG + j;
  float zi = g_zx_dec[zo];
  float zj = g_zx_dec[zo+1024];
  float zf = g_zx_dec[zo+2048];
  float zoo = g_zx_dec[zo+3072];
#pragma unroll 4
  for (int s = 0; s < ns; s++) {
    size_t po = (size_t)(s*16 + b) * NG + j;
    zi += g_zpart[po];
    zj += g_zpart[po+1024];
    zf += g_zpart[po+2048];
    zoo += g_zpart[po+3072];
  }
  float cn = g_c[idx] * sigm(zf + 1.f) + sigm(zi) * ftanh(zj);
  float hn = ftanh(cn) * sigm(zoo);
  g_c[idx] = cn;
  g_attn_h[b*2*NH + NH + j] = hn;
  g_h_ctx[b*2*NH + j] = hn;
  __nv_bfloat16 hh, ll;
  bsplit(hn, hh, ll);
  g_ya_hi[b*2*NH + NH + j] = hh;
  g_ya_lo[b*2*NH + NH + j] = ll;
  g_yc_hi[b*2*NH + j] = hh;
  g_yc_lo[b*2*NH + j] = ll;
}

// scores: skip masked rows entirely (avg enc_len ~ T/2)
__global__ __launch_bounds__(256) void attn_scores(
    const int* __restrict__ enc_len, const float* __restrict__ v_att)
{
  __shared__ float sq[NH];
  __shared__ float sv[NH];
  int b = blockIdx.x >> 3;
  int tg = blockIdx.x & 7;
  int tid = threadIdx.x;
  int L = enc_len[b];
  bool anyrow = (tg * 8) < L;
  if (anyrow) {
    for (int hh = tid; hh < NH; hh += 256) {
      float qv = 0.f;
#pragma unroll 4
      for (int s = 0; s < 16; s++) qv += g_qapart[(size_t)(s*16 + b) * 2*NH + hh];
      sq[hh] = qv;
      sv[hh] = v_att[hh];
    }
  }
  __syncthreads();
  int wid = tid >> 5;
  int lane = tid & 31;
  int tt = tg * 8 + wid;
  if (tt < L) {
    const float* krow = g_keys + (size_t)(b*NT + tt) * NH;
    float acc = 0.f;
    for (int h0 = lane; h0 < NH; h0 += 32)
      acc += ftanh(krow[h0] + sq[h0]) * sv[h0];
#pragma unroll
    for (int o = 16; o; o >>= 1) acc += __shfl_xor_sync(0xffffffffu, acc, o);
    if (lane == 0) g_scores[b*NT + tt] = acc;
  } else if (lane == 0) {
    g_scores[b*NT + tt] = -1e9f;
  }
}

// softmax + attn2 = (h2@Wa1) + sum_t align_t * premem[t] ; writes carries + dec_out
__global__ __launch_bounds__(256) void softmax_attn2(int t, const int* __restrict__ dec_len)
{
  __shared__ float sal[NT];
  int b = blockIdx.x >> 2;
  int hc = blockIdx.x & 3;
  int tid = threadIdx.x;
  if (tid < NT) sal[tid] = g_scores[b*NT + tid];
  __syncthreads();
  float mx = -3e38f;
#pragma unroll
  for (int t2 = 0; t2 < NT; t2++) mx = fmaxf(mx, sal[t2]);
  __syncthreads();
  if (tid < NT) sal[tid] = __expf(sal[tid] - mx);
  __syncthreads();
  float sum = 0.f;
#pragma unroll
  for (int t2 = 0; t2 < NT; t2++) sum += sal[t2];
  float inv = 1.f / sum;
  int j = hc * 256 + tid;
  float ha = 0.f;
#pragma unroll 4
  for (int s = 0; s < 16; s++) ha += g_qapart[(size_t)(s*16 + b) * 2*NH + NH + j];
  const float* pm = g_premem + (size_t)b * NT * NH + j;
  float cx = 0.f;
#pragma unroll 8
  for (int t2 = 0; t2 < NT; t2++) cx += sal[t2] * pm[(size_t)t2 * NH];
  float a = ha + cx * inv;
  g_attn_h[b*2*NH + j] = a;
  bsplit(a, g_ya_hi[b*2*NH + j], g_ya_lo[b*2*NH + j]);
  g_dec_out[(size_t)(b*NT + t) * NH + j] = (t >= dec_len[b]) ? 0.f : a;
}

// =====================================================================
// Host launch
// =====================================================================
extern "C" void kernel_launch(void* const* d_in, const int* in_sizes, int n_in,
                              void* d_out, int out_size)
{
  const int*   enc_in      = (const int*)d_in[0];
  const int*   dec_in      = (const int*)d_in[1];
  const int*   enc_len     = (const int*)d_in[2];
  const int*   dec_len     = (const int*)d_in[3];
  const float* embedding   = (const float*)d_in[4];
  const float* enc_kernel  = (const float*)d_in[5];
  const float* enc_bias    = (const float*)d_in[6];
  const float* dec_kernel  = (const float*)d_in[7];
  const float* dec_bias    = (const float*)d_in[8];
  const float* Wm          = (const float*)d_in[9];
  const float* Wq          = (const float*)d_in[10];
  const float* v_att       = (const float*)d_in[11];
  const float* attn_kernel = (const float*)d_in[12];
  const float* out_kernel  = (const float*)d_in[13];
  float* out = (float*)d_out;
  (void)in_sizes;
  (void)n_in;
  (void)out_size;

  float *zx_enc, *zx_dec, *mem, *keys, *premem, *dec_o, *zpart, *qapart;
  int *rowscat, *mpad;
  __nv_bfloat16 *whi, *wlo, *ahi, *alo, *rwhi, *rwlo;
  __nv_bfloat16 *yehi, *yelo, *yahi, *yalo, *ychi, *yclo;
  cudaGetSymbolAddress((void**)&zx_enc, g_zx_enc);
  cudaGetSymbolAddress((void**)&zx_dec, g_zx_dec);
  cudaGetSymbolAddress((void**)&mem,    g_memory);
  cudaGetSymbolAddress((void**)&keys,   g_keys);
  cudaGetSymbolAddress((void**)&premem, g_premem);
  cudaGetSymbolAddress((void**)&dec_o,  g_dec_out);
  cudaGetSymbolAddress((void**)&zpart,  g_zpart);
  cudaGetSymbolAddress((void**)&qapart, g_qapart);
  cudaGetSymbolAddress((void**)&rowscat, g_rowscat);
  cudaGetSymbolAddress((void**)&mpad,   g_mpad);
  cudaGetSymbolAddress((void**)&whi,    g_Whi);
  cudaGetSymbolAddress((void**)&wlo,    g_Wlo);
  cudaGetSymbolAddress((void**)&ahi,    g_Ahi);
  cudaGetSymbolAddress((void**)&alo,    g_Alo);
  cudaGetSymbolAddress((void**)&rwhi,   g_RWhi);
  cudaGetSymbolAddress((void**)&rwlo,   g_RWlo);
  cudaGetSymbolAddress((void**)&yehi,   g_ye_hi);
  cudaGetSymbolAddress((void**)&yelo,   g_ye_lo);
  cudaGetSymbolAddress((void**)&yahi,   g_ya_hi);
  cudaGetSymbolAddress((void**)&yalo,   g_ya_lo);
  cudaGetSymbolAddress((void**)&ychi,   g_yc_hi);
  cudaGetSymbolAddress((void**)&yclo,   g_yc_lo);

  const int LOGITS_SMEM = 2*2*10240 + 2*2*4608;  // 59392
  const int SKINNY_SMEM = 16896 + 2*2*8704;      // 51712
  cudaFuncSetAttribute(logits_mma, cudaFuncAttributeMaxDynamicSharedMemorySize,
                       LOGITS_SMEM);
  cudaFuncSetAttribute(skinny_mma, cudaFuncAttributeMaxDynamicSharedMemorySize,
                       SKINNY_SMEM);

  zero_state<<<64, 256>>>();
  build_rowlist<<<1, 256>>>(dec_len);
  zero_invalid_logits<<<dim3(32, 1024), 256>>>(dec_len, out);

  // fp32 -> bf16 hi/lo weight splits (once)
  conv_split<<<NV, 256>>>(out_kernel, whi, wlo);
  conv_split<<<4096, 256>>>(enc_kernel + (size_t)NE*NG, rwhi + RW_ENC, rwlo + RW_ENC);
  conv_split<<<8192, 256>>>(dec_kernel + (size_t)NE*NG, rwhi + RW_DEC, rwlo + RW_DEC);
  conv_qa<<<2048, 256>>>(Wq, attn_kernel);

  // Zx precompute: emb-gather GEMMs [1024 x 4096 x 256] with bias
  sgemm_db<<<dim3(32, 8), 256>>>(NB*NT, NG, NE, embedding, enc_kernel, enc_bias,
                                 zx_enc, enc_in, nullptr, nullptr);
  sgemm_db<<<dim3(32, 8), 256>>>(NB*NT, NG, NE, embedding, dec_kernel, dec_bias,
                                 zx_dec, dec_in, nullptr, nullptr);

  // ---- encoder ----  (z = h @ Wrec: N=4096, K=1024, KS=8)
  for (int t = 0; t < NT; t++) {
    skinny_mma<<<dim3(32, 8), 256, SKINNY_SMEM>>>(yehi, yelo, NH,
                                                  rwhi + RW_ENC, rwlo + RW_ENC,
                                                  zpart, NG, NH);
    enc_step_gates<<<64, 256>>>(t, 8, enc_len);
  }

  // keys = memory @ Wm ; premem = memory @ Wa2   [1024 x 1024 x 1024 each]
  sgemm_db<<<dim3(8, 8), 256>>>(NB*NT, NH, NH, mem, Wm, nullptr, keys,
                                nullptr, nullptr, nullptr);
  sgemm_db<<<dim3(8, 8), 256>>>(NB*NT, NH, NH, mem, attn_kernel + (size_t)NH*NH,
                                nullptr, premem, nullptr, nullptr, nullptr);

  // ---- decoder ---- (5 launches/step)
  dec_init<<<128, 256>>>();
  for (int t = 0; t < NT; t++) {
    // z = zx + [attn|h] @ Wrec: N=4096, K=2048, KS=8
    skinny_mma<<<dim3(32, 8), 256, SKINNY_SMEM>>>(yahi, yalo, 2*NH,
                                                  rwhi + RW_DEC, rwlo + RW_DEC,
                                                  zpart, NG, 2*NH);
    dec_step_gates<<<64, 256>>>(t, 8);
    // [q | h2@Wa1] = h2 @ QA: N=2048, K=1024, KS=16
    skinny_mma<<<dim3(16, 16), 256, SKINNY_SMEM>>>(ychi, yclo, 2*NH,
                                                   rwhi + RW_QA, rwlo + RW_QA,
                                                   qapart, 2*NH, NH);
    attn_scores<<<128, 256>>>(enc_len, v_att);
    softmax_attn2<<<64, 256>>>(t, dec_len);
  }

  // compact + split dec_out rows, then tensor-core logits GEMM
  conv_A<<<1024, 256>>>();
  logits_mma<<<dim3(500, 8), 256, LOGITS_SMEM>>>(ahi, alo, whi, wlo, out,
                                                 rowscat, mpad);
}